// round 10
// baseline (speedup 1.0000x reference)
#include <cuda_runtime.h>
#include <cuda_bf16.h>
#include <cstdint>
#include <cstddef>

#define DIMC   384
#define HEADS  12
#define HD     32
#define NTOK   49
#define BWIN   4096
#define NWIN   256
#define MROWS  (BWIN * NTOK)
#define QKVN   (3 * DIMC)
#define QSCALE 0.17677669529663687f

__device__ __nv_bfloat16 g_qh[(size_t)MROWS * QKVN];   // qkv hi (q pre-scaled)
__device__ __nv_bfloat16 g_ql[(size_t)MROWS * QKVN];   // qkv lo
__device__ __nv_bfloat16 g_xhi[(size_t)MROWS * DIMC];
__device__ __nv_bfloat16 g_xlo[(size_t)MROWS * DIMC];
__device__ __nv_bfloat16 g_ahi[(size_t)MROWS * DIMC];
__device__ __nv_bfloat16 g_alo[(size_t)MROWS * DIMC];
__device__ __nv_bfloat16 g_wt_hi[(size_t)(QKVN + DIMC) * DIMC];
__device__ __nv_bfloat16 g_wt_lo[(size_t)(QKVN + DIMC) * DIMC];
__device__ float g_comb[(size_t)NWIN * HEADS * NTOK * 64 + 4096];

__device__ __forceinline__ uint32_t smem_u32(const void* p) {
    uint32_t a;
    asm("{ .reg .u64 t; cvta.to.shared.u64 t, %1; cvt.u32.u64 %0, t; }"
        : "=r"(a) : "l"(p));
    return a;
}
__device__ __forceinline__ uint32_t sw128(uint32_t off) {
    return off ^ ((off >> 3) & 0x70);
}
__device__ __forceinline__ void ldsm4(uint32_t (&r)[4], uint32_t addr) {
    asm volatile("ldmatrix.sync.aligned.m8n8.x4.shared.b16 {%0,%1,%2,%3}, [%4];"
        : "=r"(r[0]), "=r"(r[1]), "=r"(r[2]), "=r"(r[3]) : "r"(addr));
}
__device__ __forceinline__ void ldsm4t(uint32_t (&r)[4], uint32_t addr) {
    asm volatile("ldmatrix.sync.aligned.m8n8.x4.trans.shared.b16 {%0,%1,%2,%3}, [%4];"
        : "=r"(r[0]), "=r"(r[1]), "=r"(r[2]), "=r"(r[3]) : "r"(addr));
}
__device__ __forceinline__ void mma16816(float (&d)[4], const uint32_t (&a)[4],
                                         uint32_t b0, uint32_t b1) {
    asm volatile(
        "mma.sync.aligned.m16n8k16.row.col.f32.bf16.bf16.f32 "
        "{%0,%1,%2,%3}, {%4,%5,%6,%7}, {%8,%9}, {%0,%1,%2,%3};"
        : "+f"(d[0]), "+f"(d[1]), "+f"(d[2]), "+f"(d[3])
        : "r"(a[0]), "r"(a[1]), "r"(a[2]), "r"(a[3]), "r"(b0), "r"(b1));
}
__device__ __forceinline__ void cp16(uint32_t dst, const void* src) {
    asm volatile("cp.async.cg.shared.global [%0], [%1], 16;"
                 :: "r"(dst), "l"(src));
}
#define CP_COMMIT() asm volatile("cp.async.commit_group;" ::: "memory")
#define CP_WAIT1()  asm volatile("cp.async.wait_group 1;" ::: "memory")
#define CP_WAIT0()  asm volatile("cp.async.wait_group 0;" ::: "memory")

__device__ __forceinline__ void split2(float x, float y, uint32_t& h, uint32_t& l) {
    __nv_bfloat162 hp = __floats2bfloat162_rn(x, y);
    __nv_bfloat162 lp = __floats2bfloat162_rn(x - __low2float(hp),
                                              y - __high2float(hp));
    h = *(uint32_t*)&hp;
    l = *(uint32_t*)&lp;
}

// ------------------------------- prep kernels -------------------------------
__global__ void prep_w_kernel(const float* __restrict__ W,
                              __nv_bfloat16* __restrict__ hi,
                              __nv_bfloat16* __restrict__ lo, int K, int N) {
    int idx = blockIdx.x * blockDim.x + threadIdx.x;
    if (idx >= N * K) return;
    int n = idx / K, k = idx % K;
    float x = W[(size_t)k * N + n];
    __nv_bfloat16 h = __float2bfloat16(x);
    hi[idx] = h;
    lo[idx] = __float2bfloat16(x - __bfloat162float(h));
}

__global__ void prep_x_kernel(const float* __restrict__ x,
                              __nv_bfloat16* __restrict__ hi,
                              __nv_bfloat16* __restrict__ lo, size_t n4) {
    size_t i = (size_t)blockIdx.x * blockDim.x + threadIdx.x;
    if (i >= n4) return;
    float4 xv = ((const float4*)x)[i];
    uint32_t h0, l0, h1, l1;
    split2(xv.x, xv.y, h0, l0);
    split2(xv.z, xv.w, h1, l1);
    ((uint2*)hi)[i] = make_uint2(h0, h1);
    ((uint2*)lo)[i] = make_uint2(l0, l1);
}

// comb[w][h][R][C64] = mask[w][R][C] + clip(bias,+-5); 0 for C>=49
__global__ void prep_comb_kernel(const float* __restrict__ mask,
                                 const float* __restrict__ table,
                                 const int* __restrict__ idx,
                                 float* __restrict__ out) {
    int e = blockIdx.x * blockDim.x + threadIdx.x;
    if (e >= NWIN * HEADS * NTOK * 64) return;
    int C = e & 63, R = (e >> 6) % NTOK;
    int wh = e / (NTOK * 64);
    int w = wh / HEADS, h = wh % HEADS;
    float v = 0.f;
    if (C < NTOK) {
        float b = table[idx[R * NTOK + C] * HEADS + h];
        v = mask[(size_t)w * NTOK * NTOK + R * NTOK + C]
          + fminf(fmaxf(b, -5.f), 5.f);
    }
    out[e] = v;
}

// ---------------- HMMA bf16-split GEMM: BM=256, BN=128, BK=32, 3 stages -----
// 256 threads = 8 warps (4m x 2n), warp tile 64x64.
// Stage 48KB: A 256x[hi32|lo32]bf16 rows (32KB) + B 128 rows (16KB), SW128.
#define GEMM_SMEM_BYTES (3 * 49152)

template <bool QKV, bool SPLIT>
__global__ __launch_bounds__(256, 1) void mma_gemm(
    const __nv_bfloat16* __restrict__ Ahi, const __nv_bfloat16* __restrict__ Alo,
    const __nv_bfloat16* __restrict__ Bhi, const __nv_bfloat16* __restrict__ Blo,
    const float* __restrict__ bias, float* __restrict__ C,
    __nv_bfloat16* __restrict__ Chi, __nv_bfloat16* __restrict__ Clo,
    int M, int N, int K)
{
    extern __shared__ char smem[];
    const uint32_t sb = smem_u32(smem);
    const int tid = threadIdx.x, lane = tid & 31, wid = tid >> 5;
    const int wm = wid & 3, wn = wid >> 2;
    const int bm = blockIdx.y * 256, bn = blockIdx.x * 128;
    const int NCH = K / 32;            // 12
    const int brow = tid >> 1, bhalf = tid & 1;   // B staging map

    auto cp_stage = [&](int s, int ch) {
        const int k0 = ch * 32;
        const uint32_t st = sb + s * 49152;
        // A: thread -> its own row (256 rows), 4 hi + 4 lo chunks of 16B
        {
            const size_t ga = (size_t)(bm + tid) * K + k0;
            #pragma unroll
            for (int c = 0; c < 4; c++) {
                cp16(st + sw128((uint32_t)(tid * 128 + c * 16)),      Ahi + ga + c * 8);
                cp16(st + sw128((uint32_t)(tid * 128 + 64 + c * 16)), Alo + ga + c * 8);
            }
        }
        // B: 128 rows, 2 threads per row, each 2 hi + 2 lo chunks
        {
            const uint32_t bst = st + 32768;
            const size_t gb = (size_t)(bn + brow) * K + k0 + bhalf * 16;
            #pragma unroll
            for (int i = 0; i < 2; i++) {
                const uint32_t co = (uint32_t)((bhalf * 2 + i) * 16);
                cp16(bst + sw128((uint32_t)(brow * 128) + co),      Bhi + gb + i * 8);
                cp16(bst + sw128((uint32_t)(brow * 128 + 64) + co), Blo + gb + i * 8);
            }
        }
    };

    float acc[4][8][4] = {};

    auto domma = [&](int s) {
        const uint32_t sA = sb + s * 49152, sB = sA + 32768;
        #pragma unroll
        for (int ks = 0; ks < 2; ks++) {
            const int chi = (2 * ks + (lane >> 4)) * 16;
            const int clo = chi + 64;
            uint32_t ah[4][4], al[4][4];
            #pragma unroll
            for (int mt = 0; mt < 4; mt++) {
                const int r = wm * 64 + mt * 16 + (lane & 15);
                ldsm4(ah[mt], sA + sw128((uint32_t)(r * 128 + chi)));
                ldsm4(al[mt], sA + sw128((uint32_t)(r * 128 + clo)));
            }
            #pragma unroll
            for (int g = 0; g < 4; g++) {
                const int r = wn * 64 + g * 16 + (lane & 15);
                uint32_t bh[4], bl[4];
                ldsm4(bh, sB + sw128((uint32_t)(r * 128 + chi)));
                ldsm4(bl, sB + sw128((uint32_t)(r * 128 + clo)));
                #pragma unroll
                for (int o = 0; o < 2; o++) {
                    const int nt = g * 2 + o;
                    #pragma unroll
                    for (int mt = 0; mt < 4; mt++) {
                        mma16816(acc[mt][nt], ah[mt], bh[o], bh[o + 2]);
                        mma16816(acc[mt][nt], al[mt], bh[o], bh[o + 2]);
                        mma16816(acc[mt][nt], ah[mt], bl[o], bl[o + 2]);
                    }
                }
            }
        }
    };

    cp_stage(0, 0); CP_COMMIT();
    cp_stage(1, 1); CP_COMMIT();
    for (int ch = 0; ch < NCH; ch++) {
        const int s = ch % 3;
        CP_WAIT1();
        __syncthreads();
        if (ch + 2 < NCH) cp_stage((ch + 2) % 3, ch + 2);
        CP_COMMIT();
        domma(s);
    }

    const float qs = (QKV && bn < DIMC) ? QSCALE : 1.0f;
    #pragma unroll
    for (int mt = 0; mt < 4; mt++) {
        const int r0 = bm + wm * 64 + mt * 16 + (lane >> 2);
        #pragma unroll
        for (int nt = 0; nt < 8; nt++) {
            const int c0 = bn + wn * 64 + nt * 8 + (lane & 3) * 2;
            const float2 bv = *(const float2*)(bias + c0);
            float x0 = (acc[mt][nt][0] + bv.x) * qs;
            float y0 = (acc[mt][nt][1] + bv.y) * qs;
            float x1 = (acc[mt][nt][2] + bv.x) * qs;
            float y1 = (acc[mt][nt][3] + bv.y) * qs;
            if (SPLIT) {
                uint32_t hp, lp;
                split2(x0, y0, hp, lp);
                *(uint32_t*)(Chi + (size_t)r0 * N + c0) = hp;
                *(uint32_t*)(Clo + (size_t)r0 * N + c0) = lp;
                split2(x1, y1, hp, lp);
                *(uint32_t*)(Chi + (size_t)(r0 + 8) * N + c0) = hp;
                *(uint32_t*)(Clo + (size_t)(r0 + 8) * N + c0) = lp;
            } else {
                *(float2*)(C + (size_t)r0 * N + c0)       = make_float2(x0, y0);
                *(float2*)(C + (size_t)(r0 + 8) * N + c0) = make_float2(x1, y1);
            }
        }
    }
}

// ---------------- Attention v3 (unchanged from R8) --------------------------
#define ATTN_SMEM_BYTES (6 * 16384)

__global__ __launch_bounds__(128, 2) void attn_mma_kernel(
    const __nv_bfloat16* __restrict__ qh_g, const __nv_bfloat16* __restrict__ ql_g,
    const float* __restrict__ comb,
    __nv_bfloat16* __restrict__ ohi, __nv_bfloat16* __restrict__ olo)
{
    extern __shared__ char smem[];
    const uint32_t sb = smem_u32(smem);
    const int tid = threadIdx.x, lane = tid & 31, wid = tid >> 5;
    const int b = blockIdx.x / 3, hg = blockIdx.x % 3;
    const int h = hg * 4 + wid;

    for (int i = tid; i < 12 * 15 * 8; i += 128) {
        const int t = i / 120, rr = 49 + (i % 120) / 8, q4 = i % 8;
        *(uint4*)(smem + t * 8192 + sw128((uint32_t)(rr * 128 + q4 * 16))) =
            make_uint4(0, 0, 0, 0);
    }
    {
        const size_t rowbase = (size_t)b * NTOK * QKVN;
        for (int i = tid; i < NTOK * 96; i += 128) {
            const int n = i / 96, rem = i % 96;
            const int mh = rem >> 4, ck = rem & 15;
            const int mat = mh >> 1, half = mh & 1;
            const __nv_bfloat16* src = (half ? ql_g : qh_g)
                + rowbase + (size_t)n * QKVN + mat * DIMC + hg * 128 + ck * 8;
            const uint32_t dst = sb + mh * 16384 + (ck >> 3) * 8192
                               + sw128((uint32_t)(n * 128 + (ck & 7) * 16));
            cp16(dst, src);
        }
    }
    CP_COMMIT(); CP_WAIT0();
    __syncthreads();

    const int t = wid >> 1, th = wid & 1;
    const uint32_t Qh = sb + t * 8192;
    const uint32_t Ql = Qh + 16384, Kh = Qh + 32768, Kl = Qh + 49152;
    const uint32_t Vh = Qh + 65536, Vl = Qh + 81920;

    float acc[4][7][4] = {};
    #pragma unroll
    for (int ks = 0; ks < 2; ks++) {
        const uint32_t qb = (uint32_t)(th * 64 + (2 * ks + (lane >> 4)) * 16);
        uint32_t qfh[4][4], qfl[4][4];
        #pragma unroll
        for (int mt = 0; mt < 4; mt++) {
            const int r = mt * 16 + (lane & 15);
            ldsm4(qfh[mt], Qh + sw128((uint32_t)(r * 128) + qb));
            ldsm4(qfl[mt], Ql + sw128((uint32_t)(r * 128) + qb));
        }
        #pragma unroll
        for (int g = 0; g < 4; g++) {
            const int rk = g * 16 + (lane & 15);
            uint32_t kfh[4], kfl[4];
            ldsm4(kfh, Kh + sw128((uint32_t)(rk * 128) + qb));
            ldsm4(kfl, Kl + sw128((uint32_t)(rk * 128) + qb));
            #pragma unroll
            for (int o = 0; o < 2; o++) {
                const int nt = g * 2 + o;
                if (nt == 7) continue;
                #pragma unroll
                for (int mt = 0; mt < 4; mt++) {
                    mma16816(acc[mt][nt], qfh[mt], kfh[o], kfh[o + 2]);
                    mma16816(acc[mt][nt], qfl[mt], kfh[o], kfh[o + 2]);
                    mma16816(acc[mt][nt], qfh[mt], kfl[o], kfl[o + 2]);
                }
            }
        }
    }

    const float* cw = comb + ((size_t)(b & (NWIN - 1)) * HEADS + h) * (NTOK * 64);
    #pragma unroll
    for (int mt = 0; mt < 4; mt++)
        #pragma unroll
        for (int nt = 0; nt < 7; nt++) {
            const int C0 = nt * 8 + 2 * (lane & 3);
            #pragma unroll
            for (int rh = 0; rh < 2; rh++) {
                const int R = mt * 16 + (lane >> 2) + rh * 8;
                const float2 cb = *(const float2*)(cw + R * 64 + C0);
                float s0 = fminf(fmaxf(acc[mt][nt][rh*2]   + cb.x, -10.f), 10.f);
                float s1 = fminf(fmaxf(acc[mt][nt][rh*2+1] + cb.y, -10.f), 10.f);
                if (nt == 6) {
                    if (C0 >= NTOK)     s0 = -1e30f;
                    if (C0 + 1 >= NTOK) s1 = -1e30f;
                }
                acc[mt][nt][rh*2]   = s0;
                acc[mt][nt][rh*2+1] = s1;
            }
        }

    #pragma unroll
    for (int mt = 0; mt < 4; mt++)
        #pragma unroll
        for (int rh = 0; rh < 2; rh++) {
            float mx = -1e30f;
            #pragma unroll
            for (int nt = 0; nt < 7; nt++)
                mx = fmaxf(mx, fmaxf(acc[mt][nt][rh*2], acc[mt][nt][rh*2+1]));
            mx = fmaxf(mx, __shfl_xor_sync(0xffffffffu, mx, 1));
            mx = fmaxf(mx, __shfl_xor_sync(0xffffffffu, mx, 2));
            float sum = 0.f;
            #pragma unroll
            for (int nt = 0; nt < 7; nt++) {
                float e0 = __expf(acc[mt][nt][rh*2]   - mx);
                float e1 = __expf(acc[mt][nt][rh*2+1] - mx);
                acc[mt][nt][rh*2] = e0; acc[mt][nt][rh*2+1] = e1;
                sum += e0 + e1;
            }
            sum += __shfl_xor_sync(0xffffffffu, sum, 1);
            sum += __shfl_xor_sync(0xffffffffu, sum, 2);
            const float inv = 1.f / sum;
            #pragma unroll
            for (int nt = 0; nt < 7; nt++) {
                acc[mt][nt][rh*2] *= inv; acc[mt][nt][rh*2+1] *= inv;
            }
        }

    float oacc[4][4][4] = {};
    #pragma unroll
    for (int kk = 0; kk < 4; kk++) {
        uint32_t vfh[2][4], vfl[2][4];
        #pragma unroll
        for (int dp = 0; dp < 2; dp++) {
            const int rm = kk * 16 + (lane & 15);
            const uint32_t vb = (uint32_t)(th * 64 + dp * 32 + (lane >> 4) * 16);
            ldsm4t(vfh[dp], Vh + sw128((uint32_t)(rm * 128) + vb));
            ldsm4t(vfl[dp], Vl + sw128((uint32_t)(rm * 128) + vb));
        }
        const int nta = kk * 2, ntb = kk * 2 + 1;
        #pragma unroll
        for (int mt = 0; mt < 4; mt++) {
            uint32_t ph[4], pl[4];
            split2(acc[mt][nta][0], acc[mt][nta][1], ph[0], pl[0]);
            split2(acc[mt][nta][2], acc[mt][nta][3], ph[1], pl[1]);
            if (ntb < 7) {
                split2(acc[mt][ntb][0], acc[mt][ntb][1], ph[2], pl[2]);
                split2(acc[mt][ntb][2], acc[mt][ntb][3], ph[3], pl[3]);
            } else {
                ph[2] = ph[3] = pl[2] = pl[3] = 0u;
            }
            #pragma unroll
            for (int dp = 0; dp < 2; dp++)
                #pragma unroll
                for (int o = 0; o < 2; o++) {
                    const int dt = dp * 2 + o;
                    mma16816(oacc[mt][dt], ph, vfh[dp][2*o], vfh[dp][2*o+1]);
                    mma16816(oacc[mt][dt], pl, vfh[dp][2*o], vfh[dp][2*o+1]);
                    mma16816(oacc[mt][dt], ph, vfl[dp][2*o], vfl[dp][2*o+1]);
                }
        }
    }

    const size_t ob = (size_t)b * NTOK * DIMC + h * HD;
    #pragma unroll
    for (int mt = 0; mt < 4; mt++)
        #pragma unroll
        for (int rh = 0; rh < 2; rh++) {
            const int R = mt * 16 + (lane >> 2) + rh * 8;
            if (R < NTOK) {
                #pragma unroll
                for (int dt = 0; dt < 4; dt++) {
                    uint32_t hp, lp;
                    split2(oacc[mt][dt][rh*2], oacc[mt][dt][rh*2+1], hp, lp);
                    const size_t o = ob + (size_t)R * DIMC + dt * 8 + 2 * (lane & 3);
                    *(uint32_t*)(ohi + o) = hp;
                    *(uint32_t*)(olo + o) = lp;
                }
            }
        }
}

// ---------------------------------------------------------------------------
extern "C" void kernel_launch(void* const* d_in, const int* in_sizes, int n_in,
                              void* d_out, int out_size)
{
    const float* x         = (const float*)d_in[0];
    const float* mask      = (const float*)d_in[1];
    const float* qkv_w     = (const float*)d_in[2];
    const float* qkv_b     = (const float*)d_in[3];
    const float* proj_w    = (const float*)d_in[4];
    const float* proj_b    = (const float*)d_in[5];
    const float* rel_table = (const float*)d_in[6];
    const int*   rel_index = (const int*)d_in[7];
    float*       out       = (float*)d_out;

    float* combbuf = nullptr;
    __nv_bfloat16 *qh, *ql, *xhi, *xlo, *ahi, *alo, *wt_hi, *wt_lo;
    cudaGetSymbolAddress((void**)&combbuf, g_comb);
    cudaGetSymbolAddress((void**)&qh, g_qh);
    cudaGetSymbolAddress((void**)&ql, g_ql);
    cudaGetSymbolAddress((void**)&xhi, g_xhi);
    cudaGetSymbolAddress((void**)&xlo, g_xlo);
    cudaGetSymbolAddress((void**)&ahi, g_ahi);
    cudaGetSymbolAddress((void**)&alo, g_alo);
    cudaGetSymbolAddress((void**)&wt_hi, g_wt_hi);
    cudaGetSymbolAddress((void**)&wt_lo, g_wt_lo);

    static int _once = []() {
        cudaFuncSetAttribute(mma_gemm<true, true>,
            cudaFuncAttributeMaxDynamicSharedMemorySize, GEMM_SMEM_BYTES);
        cudaFuncSetAttribute(mma_gemm<false, false>,
            cudaFuncAttributeMaxDynamicSharedMemorySize, GEMM_SMEM_BYTES);
        cudaFuncSetAttribute(attn_mma_kernel,
            cudaFuncAttributeMaxDynamicSharedMemorySize, ATTN_SMEM_BYTES);
        return 0;
    }();
    (void)_once;

    const size_t proj_off = (size_t)QKVN * DIMC;

    prep_w_kernel<<<(QKVN * DIMC + 255) / 256, 256>>>(qkv_w, wt_hi, wt_lo,
                                                      DIMC, QKVN);
    prep_w_kernel<<<(DIMC * DIMC + 255) / 256, 256>>>(
        proj_w, wt_hi + proj_off, wt_lo + proj_off, DIMC, DIMC);
    prep_comb_kernel<<<(NWIN * HEADS * NTOK * 64 + 255) / 256, 256>>>(
        mask, rel_table, rel_index, combbuf);
    {
        const size_t n4 = (size_t)MROWS * DIMC / 4;
        prep_x_kernel<<<(unsigned)((n4 + 255) / 256), 256>>>(x, xhi, xlo, n4);
    }

    {   // QKV GEMM -> bf16 hi/lo
        dim3 grid(QKVN / 128, MROWS / 256);  // (9, 784)
        mma_gemm<true, true><<<grid, 256, GEMM_SMEM_BYTES>>>(
            xhi, xlo, wt_hi, wt_lo, qkv_b, nullptr, qh, ql, MROWS, QKVN, DIMC);
    }

    attn_mma_kernel<<<BWIN * 3, 128, ATTN_SMEM_BYTES>>>(qh, ql, combbuf,
                                                        ahi, alo);

    {   // proj GEMM -> fp32 out
        dim3 grid(DIMC / 128, MROWS / 256);  // (3, 784)
        mma_gemm<false, false><<<grid, 256, GEMM_SMEM_BYTES>>>(
            ahi, alo, wt_hi + proj_off, wt_lo + proj_off, proj_b, out,
            nullptr, nullptr, MROWS, DIMC, DIMC);
    }
}

// round 11
// speedup vs baseline: 1.6639x; 1.6639x over previous
#include <cuda_runtime.h>
#include <cuda_bf16.h>
#include <cuda_fp16.h>
#include <cstdint>
#include <cstddef>

#define DIMC   384
#define HEADS  12
#define HD     32
#define NTOK   49
#define BWIN   4096
#define NWIN   256
#define MROWS  (BWIN * NTOK)
#define QKVN   (3 * DIMC)
#define QSCALE 0.17677669529663687f

__device__ __nv_bfloat16 g_qh[(size_t)MROWS * QKVN];   // qkv hi (q pre-scaled)
__device__ __nv_bfloat16 g_ql[(size_t)MROWS * QKVN];   // qkv lo
__device__ __half g_x16[(size_t)MROWS * DIMC];         // x as fp16
__device__ __half g_a16[(size_t)MROWS * DIMC];         // attn out as fp16
__device__ __half g_wh[(size_t)(QKVN + DIMC) * DIMC];  // W^T fp16 hi
__device__ __half g_wl[(size_t)(QKVN + DIMC) * DIMC];  // W^T fp16 lo
__device__ float g_comb[(size_t)NWIN * HEADS * NTOK * 64 + 4096];

__device__ __forceinline__ uint32_t smem_u32(const void* p) {
    uint32_t a;
    asm("{ .reg .u64 t; cvta.to.shared.u64 t, %1; cvt.u32.u64 %0, t; }"
        : "=r"(a) : "l"(p));
    return a;
}
__device__ __forceinline__ uint32_t sw128(uint32_t off) {
    return off ^ ((off >> 3) & 0x70);
}
__device__ __forceinline__ void ldsm4(uint32_t (&r)[4], uint32_t addr) {
    asm volatile("ldmatrix.sync.aligned.m8n8.x4.shared.b16 {%0,%1,%2,%3}, [%4];"
        : "=r"(r[0]), "=r"(r[1]), "=r"(r[2]), "=r"(r[3]) : "r"(addr));
}
__device__ __forceinline__ void ldsm4t(uint32_t (&r)[4], uint32_t addr) {
    asm volatile("ldmatrix.sync.aligned.m8n8.x4.trans.shared.b16 {%0,%1,%2,%3}, [%4];"
        : "=r"(r[0]), "=r"(r[1]), "=r"(r[2]), "=r"(r[3]) : "r"(addr));
}
// bf16 mma (attention)
__device__ __forceinline__ void mma_bf16(float (&d)[4], const uint32_t (&a)[4],
                                         uint32_t b0, uint32_t b1) {
    asm volatile(
        "mma.sync.aligned.m16n8k16.row.col.f32.bf16.bf16.f32 "
        "{%0,%1,%2,%3}, {%4,%5,%6,%7}, {%8,%9}, {%0,%1,%2,%3};"
        : "+f"(d[0]), "+f"(d[1]), "+f"(d[2]), "+f"(d[3])
        : "r"(a[0]), "r"(a[1]), "r"(a[2]), "r"(a[3]), "r"(b0), "r"(b1));
}
// fp16 mma (GEMMs)
__device__ __forceinline__ void mma_f16(float (&d)[4], const uint32_t (&a)[4],
                                        uint32_t b0, uint32_t b1) {
    asm volatile(
        "mma.sync.aligned.m16n8k16.row.col.f32.f16.f16.f32 "
        "{%0,%1,%2,%3}, {%4,%5,%6,%7}, {%8,%9}, {%0,%1,%2,%3};"
        : "+f"(d[0]), "+f"(d[1]), "+f"(d[2]), "+f"(d[3])
        : "r"(a[0]), "r"(a[1]), "r"(a[2]), "r"(a[3]), "r"(b0), "r"(b1));
}
__device__ __forceinline__ void cp16(uint32_t dst, const void* src) {
    asm volatile("cp.async.cg.shared.global [%0], [%1], 16;"
                 :: "r"(dst), "l"(src));
}
#define CP_COMMIT() asm volatile("cp.async.commit_group;" ::: "memory")
#define CP_WAIT1()  asm volatile("cp.async.wait_group 1;" ::: "memory")
#define CP_WAIT0()  asm volatile("cp.async.wait_group 0;" ::: "memory")

// bf16 hi/lo split (attention path)
__device__ __forceinline__ void split2(float x, float y, uint32_t& h, uint32_t& l) {
    __nv_bfloat162 hp = __floats2bfloat162_rn(x, y);
    __nv_bfloat162 lp = __floats2bfloat162_rn(x - __low2float(hp),
                                              y - __high2float(hp));
    h = *(uint32_t*)&hp;
    l = *(uint32_t*)&lp;
}

// ------------------------------- prep kernels -------------------------------
__global__ void prep_w_kernel(const float* __restrict__ W,
                              __half* __restrict__ hi,
                              __half* __restrict__ lo, int K, int N) {
    int idx = blockIdx.x * blockDim.x + threadIdx.x;
    if (idx >= N * K) return;
    int n = idx / K, k = idx % K;
    float x = W[(size_t)k * N + n];
    __half h = __float2half_rn(x);
    hi[idx] = h;
    lo[idx] = __float2half_rn(x - __half2float(h));
}

__global__ void prep_x_kernel(const float* __restrict__ x,
                              __half* __restrict__ x16, size_t n4) {
    size_t i = (size_t)blockIdx.x * blockDim.x + threadIdx.x;
    if (i >= n4) return;
    float4 xv = ((const float4*)x)[i];
    __half2 a = __floats2half2_rn(xv.x, xv.y);
    __half2 b = __floats2half2_rn(xv.z, xv.w);
    ((uint2*)x16)[i] = make_uint2(*(uint32_t*)&a, *(uint32_t*)&b);
}

// comb[w][h][R][C64] = mask[w][R][C] + clip(bias,+-5); 0 for C>=49
__global__ void prep_comb_kernel(const float* __restrict__ mask,
                                 const float* __restrict__ table,
                                 const int* __restrict__ idx,
                                 float* __restrict__ out) {
    int e = blockIdx.x * blockDim.x + threadIdx.x;
    if (e >= NWIN * HEADS * NTOK * 64) return;
    int C = e & 63, R = (e >> 6) % NTOK;
    int wh = e / (NTOK * 64);
    int w = wh / HEADS, h = wh % HEADS;
    float v = 0.f;
    if (C < NTOK) {
        float b = table[idx[R * NTOK + C] * HEADS + h];
        v = mask[(size_t)w * NTOK * NTOK + R * NTOK + C]
          + fminf(fmaxf(b, -5.f), 5.f);
    }
    out[e] = v;
}

// ---- fp16 GEMM: C = A @ Wt^T + bias. A single fp16, Wt fp16 hi/lo (2 MMAs).
// BM=BN=128, BK=64, 3 stages; stage = A 16KB + Bh 16KB + Bl 16KB = 48KB.
#define GEMM_SMEM_BYTES (3 * 49152)

template <bool QKV, bool SPLIT>
__global__ __launch_bounds__(256, 1) void mma_gemm(
    const __half* __restrict__ A16,
    const __half* __restrict__ Bhi, const __half* __restrict__ Blo,
    const float* __restrict__ bias, float* __restrict__ C,
    __nv_bfloat16* __restrict__ Chi, __nv_bfloat16* __restrict__ Clo,
    int M, int N, int K)
{
    extern __shared__ char smem[];
    const uint32_t sb = smem_u32(smem);
    const int tid = threadIdx.x, lane = tid & 31, wid = tid >> 5;
    const int wm = wid & 3, wn = wid >> 2;
    const int bm = blockIdx.y * 128, bn = blockIdx.x * 128;
    const int NCH = K / 64;
    const int crow = tid >> 3, cpos = tid & 7;

    auto cp_stage = [&](int s, int ch) {
        const int k0 = ch * 64;
        const uint32_t st = sb + s * 49152;
        #pragma unroll
        for (int t = 0; t < 4; t++) {
            const int row = t * 32 + crow;
            const uint32_t soff = sw128((uint32_t)(row * 128 + cpos * 16));
            const size_t ga = (size_t)(bm + row) * K + k0 + cpos * 8;
            const size_t gb = (size_t)(bn + row) * K + k0 + cpos * 8;
            cp16(st + soff,         A16 + ga);
            cp16(st + 16384 + soff, Bhi + gb);
            cp16(st + 32768 + soff, Blo + gb);
        }
    };

    float acc[2][8][4] = {};

    auto domma = [&](int s) {
        const uint32_t sA = sb + s * 49152;
        const uint32_t sBh = sA + 16384, sBl = sA + 32768;
        #pragma unroll
        for (int ks = 0; ks < 4; ks++) {
            const int cb = ks * 32 + (lane >> 4) * 16;
            uint32_t af[2][4];
            #pragma unroll
            for (int mt = 0; mt < 2; mt++) {
                const int r = wm * 32 + mt * 16 + (lane & 15);
                ldsm4(af[mt], sA + sw128((uint32_t)(r * 128 + cb)));
            }
            uint32_t bh[4][4], bl[4][4];
            #pragma unroll
            for (int g = 0; g < 4; g++) {
                const int r = wn * 64 + g * 16 + (lane & 15);
                const uint32_t o = sw128((uint32_t)(r * 128 + cb));
                ldsm4(bh[g], sBh + o);
                ldsm4(bl[g], sBl + o);
            }
            #pragma unroll
            for (int mt = 0; mt < 2; mt++)
                #pragma unroll
                for (int nt = 0; nt < 8; nt++) {
                    const int g = nt >> 1, o = nt & 1;
                    mma_f16(acc[mt][nt], af[mt], bh[g][o], bh[g][o + 2]);
                    mma_f16(acc[mt][nt], af[mt], bl[g][o], bl[g][o + 2]);
                }
        }
    };

    cp_stage(0, 0); CP_COMMIT();
    cp_stage(1, 1); CP_COMMIT();
    for (int ch = 0; ch < NCH; ch++) {
        const int s = ch % 3;
        CP_WAIT1();
        __syncthreads();
        if (ch + 2 < NCH) cp_stage((ch + 2) % 3, ch + 2);
        CP_COMMIT();
        domma(s);
    }

    const float qs = (QKV && bn < DIMC) ? QSCALE : 1.0f;
    #pragma unroll
    for (int mt = 0; mt < 2; mt++) {
        const int r0 = bm + wm * 32 + mt * 16 + (lane >> 2);
        #pragma unroll
        for (int nt = 0; nt < 8; nt++) {
            const int c0 = bn + wn * 64 + nt * 8 + (lane & 3) * 2;
            const float2 bv = *(const float2*)(bias + c0);
            float x0 = (acc[mt][nt][0] + bv.x) * qs;
            float y0 = (acc[mt][nt][1] + bv.y) * qs;
            float x1 = (acc[mt][nt][2] + bv.x) * qs;
            float y1 = (acc[mt][nt][3] + bv.y) * qs;
            if (SPLIT) {   // bf16 hi/lo for attention
                uint32_t hp, lp;
                split2(x0, y0, hp, lp);
                *(uint32_t*)(Chi + (size_t)r0 * N + c0) = hp;
                *(uint32_t*)(Clo + (size_t)r0 * N + c0) = lp;
                split2(x1, y1, hp, lp);
                *(uint32_t*)(Chi + (size_t)(r0 + 8) * N + c0) = hp;
                *(uint32_t*)(Clo + (size_t)(r0 + 8) * N + c0) = lp;
            } else {
                *(float2*)(C + (size_t)r0 * N + c0)       = make_float2(x0, y0);
                *(float2*)(C + (size_t)(r0 + 8) * N + c0) = make_float2(x1, y1);
            }
        }
    }
}

// ---------------- Attention (R8 structure, bf16 3-MMA; fp16 single output) --
#define ATTN_SMEM_BYTES (6 * 16384)

__global__ __launch_bounds__(128, 2) void attn_mma_kernel(
    const __nv_bfloat16* __restrict__ qh_g, const __nv_bfloat16* __restrict__ ql_g,
    const float* __restrict__ comb, __half* __restrict__ o16)
{
    extern __shared__ char smem[];
    const uint32_t sb = smem_u32(smem);
    const int tid = threadIdx.x, lane = tid & 31, wid = tid >> 5;
    const int b = blockIdx.x / 3, hg = blockIdx.x % 3;
    const int h = hg * 4 + wid;

    for (int i = tid; i < 12 * 15 * 8; i += 128) {
        const int t = i / 120, rr = 49 + (i % 120) / 8, q4 = i % 8;
        *(uint4*)(smem + t * 8192 + sw128((uint32_t)(rr * 128 + q4 * 16))) =
            make_uint4(0, 0, 0, 0);
    }
    {
        const size_t rowbase = (size_t)b * NTOK * QKVN;
        for (int i = tid; i < NTOK * 96; i += 128) {
            const int n = i / 96, rem = i % 96;
            const int mh = rem >> 4, ck = rem & 15;
            const int mat = mh >> 1, half = mh & 1;
            const __nv_bfloat16* src = (half ? ql_g : qh_g)
                + rowbase + (size_t)n * QKVN + mat * DIMC + hg * 128 + ck * 8;
            const uint32_t dst = sb + mh * 16384 + (ck >> 3) * 8192
                               + sw128((uint32_t)(n * 128 + (ck & 7) * 16));
            cp16(dst, src);
        }
    }
    CP_COMMIT(); CP_WAIT0();
    __syncthreads();

    const int t = wid >> 1, th = wid & 1;
    const uint32_t Qh = sb + t * 8192;
    const uint32_t Ql = Qh + 16384, Kh = Qh + 32768, Kl = Qh + 49152;
    const uint32_t Vh = Qh + 65536, Vl = Qh + 81920;

    float acc[4][7][4] = {};
    #pragma unroll
    for (int ks = 0; ks < 2; ks++) {
        const uint32_t qb = (uint32_t)(th * 64 + (2 * ks + (lane >> 4)) * 16);
        uint32_t qfh[4][4], qfl[4][4];
        #pragma unroll
        for (int mt = 0; mt < 4; mt++) {
            const int r = mt * 16 + (lane & 15);
            ldsm4(qfh[mt], Qh + sw128((uint32_t)(r * 128) + qb));
            ldsm4(qfl[mt], Ql + sw128((uint32_t)(r * 128) + qb));
        }
        #pragma unroll
        for (int g = 0; g < 4; g++) {
            const int rk = g * 16 + (lane & 15);
            uint32_t kfh[4], kfl[4];
            ldsm4(kfh, Kh + sw128((uint32_t)(rk * 128) + qb));
            ldsm4(kfl, Kl + sw128((uint32_t)(rk * 128) + qb));
            #pragma unroll
            for (int o = 0; o < 2; o++) {
                const int nt = g * 2 + o;
                if (nt == 7) continue;
                #pragma unroll
                for (int mt = 0; mt < 4; mt++) {
                    mma_bf16(acc[mt][nt], qfh[mt], kfh[o], kfh[o + 2]);
                    mma_bf16(acc[mt][nt], qfl[mt], kfh[o], kfh[o + 2]);
                    mma_bf16(acc[mt][nt], qfh[mt], kfl[o], kfl[o + 2]);
                }
            }
        }
    }

    const float* cw = comb + ((size_t)(b & (NWIN - 1)) * HEADS + h) * (NTOK * 64);
    #pragma unroll
    for (int mt = 0; mt < 4; mt++)
        #pragma unroll
        for (int nt = 0; nt < 7; nt++) {
            const int C0 = nt * 8 + 2 * (lane & 3);
            #pragma unroll
            for (int rh = 0; rh < 2; rh++) {
                const int R = mt * 16 + (lane >> 2) + rh * 8;
                const float2 cb = *(const float2*)(cw + R * 64 + C0);
                float s0 = fminf(fmaxf(acc[mt][nt][rh*2]   + cb.x, -10.f), 10.f);
                float s1 = fminf(fmaxf(acc[mt][nt][rh*2+1] + cb.y, -10.f), 10.f);
                if (nt == 6) {
                    if (C0 >= NTOK)     s0 = -1e30f;
                    if (C0 + 1 >= NTOK) s1 = -1e30f;
                }
                acc[mt][nt][rh*2]   = s0;
                acc[mt][nt][rh*2+1] = s1;
            }
        }

    #pragma unroll
    for (int mt = 0; mt < 4; mt++)
        #pragma unroll
        for (int rh = 0; rh < 2; rh++) {
            float mx = -1e30f;
            #pragma unroll
            for (int nt = 0; nt < 7; nt++)
                mx = fmaxf(mx, fmaxf(acc[mt][nt][rh*2], acc[mt][nt][rh*2+1]));
            mx = fmaxf(mx, __shfl_xor_sync(0xffffffffu, mx, 1));
            mx = fmaxf(mx, __shfl_xor_sync(0xffffffffu, mx, 2));
            float sum = 0.f;
            #pragma unroll
            for (int nt = 0; nt < 7; nt++) {
                float e0 = __expf(acc[mt][nt][rh*2]   - mx);
                float e1 = __expf(acc[mt][nt][rh*2+1] - mx);
                acc[mt][nt][rh*2] = e0; acc[mt][nt][rh*2+1] = e1;
                sum += e0 + e1;
            }
            sum += __shfl_xor_sync(0xffffffffu, sum, 1);
            sum += __shfl_xor_sync(0xffffffffu, sum, 2);
            const float inv = 1.f / sum;
            #pragma unroll
            for (int nt = 0; nt < 7; nt++) {
                acc[mt][nt][rh*2] *= inv; acc[mt][nt][rh*2+1] *= inv;
            }
        }

    float oacc[4][4][4] = {};
    #pragma unroll
    for (int kk = 0; kk < 4; kk++) {
        uint32_t vfh[2][4], vfl[2][4];
        #pragma unroll
        for (int dp = 0; dp < 2; dp++) {
            const int rm = kk * 16 + (lane & 15);
            const uint32_t vb = (uint32_t)(th * 64 + dp * 32 + (lane >> 4) * 16);
            ldsm4t(vfh[dp], Vh + sw128((uint32_t)(rm * 128) + vb));
            ldsm4t(vfl[dp], Vl + sw128((uint32_t)(rm * 128) + vb));
        }
        const int nta = kk * 2, ntb = kk * 2 + 1;
        #pragma unroll
        for (int mt = 0; mt < 4; mt++) {
            uint32_t ph[4], pl[4];
            split2(acc[mt][nta][0], acc[mt][nta][1], ph[0], pl[0]);
            split2(acc[mt][nta][2], acc[mt][nta][3], ph[1], pl[1]);
            if (ntb < 7) {
                split2(acc[mt][ntb][0], acc[mt][ntb][1], ph[2], pl[2]);
                split2(acc[mt][ntb][2], acc[mt][ntb][3], ph[3], pl[3]);
            } else {
                ph[2] = ph[3] = pl[2] = pl[3] = 0u;
            }
            #pragma unroll
            for (int dp = 0; dp < 2; dp++)
                #pragma unroll
                for (int o = 0; o < 2; o++) {
                    const int dt = dp * 2 + o;
                    mma_bf16(oacc[mt][dt], ph, vfh[dp][2*o], vfh[dp][2*o+1]);
                    mma_bf16(oacc[mt][dt], pl, vfh[dp][2*o], vfh[dp][2*o+1]);
                    mma_bf16(oacc[mt][dt], ph, vfl[dp][2*o], vfl[dp][2*o+1]);
                }
        }
    }

    // store single fp16 for proj GEMM
    const size_t ob = (size_t)b * NTOK * DIMC + h * HD;
    #pragma unroll
    for (int mt = 0; mt < 4; mt++)
        #pragma unroll
        for (int rh = 0; rh < 2; rh++) {
            const int R = mt * 16 + (lane >> 2) + rh * 8;
            if (R < NTOK) {
                #pragma unroll
                for (int dt = 0; dt < 4; dt++) {
                    __half2 hv = __floats2half2_rn(oacc[mt][dt][rh*2],
                                                   oacc[mt][dt][rh*2+1]);
                    const size_t o = ob + (size_t)R * DIMC + dt * 8 + 2 * (lane & 3);
                    *(uint32_t*)(o16 + o) = *(uint32_t*)&hv;
                }
            }
        }
}

// ---------------------------------------------------------------------------
extern "C" void kernel_launch(void* const* d_in, const int* in_sizes, int n_in,
                              void* d_out, int out_size)
{
    const float* x         = (const float*)d_in[0];
    const float* mask      = (const float*)d_in[1];
    const float* qkv_w     = (const float*)d_in[2];
    const float* qkv_b     = (const float*)d_in[3];
    const float* proj_w    = (const float*)d_in[4];
    const float* proj_b    = (const float*)d_in[5];
    const float* rel_table = (const float*)d_in[6];
    const int*   rel_index = (const int*)d_in[7];
    float*       out       = (float*)d_out;

    float* combbuf = nullptr;
    __nv_bfloat16 *qh, *ql;
    __half *x16, *a16, *wh, *wl;
    cudaGetSymbolAddress((void**)&combbuf, g_comb);
    cudaGetSymbolAddress((void**)&qh, g_qh);
    cudaGetSymbolAddress((void**)&ql, g_ql);
    cudaGetSymbolAddress((void**)&x16, g_x16);
    cudaGetSymbolAddress((void**)&a16, g_a16);
    cudaGetSymbolAddress((void**)&wh, g_wh);
    cudaGetSymbolAddress((void**)&wl, g_wl);

    static int _once = []() {
        cudaFuncSetAttribute(mma_gemm<true, true>,
            cudaFuncAttributeMaxDynamicSharedMemorySize, GEMM_SMEM_BYTES);
        cudaFuncSetAttribute(mma_gemm<false, false>,
            cudaFuncAttributeMaxDynamicSharedMemorySize, GEMM_SMEM_BYTES);
        cudaFuncSetAttribute(attn_mma_kernel,
            cudaFuncAttributeMaxDynamicSharedMemorySize, ATTN_SMEM_BYTES);
        return 0;
    }();
    (void)_once;

    const size_t proj_off = (size_t)QKVN * DIMC;

    prep_w_kernel<<<(QKVN * DIMC + 255) / 256, 256>>>(qkv_w, wh, wl,
                                                      DIMC, QKVN);
    prep_w_kernel<<<(DIMC * DIMC + 255) / 256, 256>>>(
        proj_w, wh + proj_off, wl + proj_off, DIMC, DIMC);
    prep_comb_kernel<<<(NWIN * HEADS * NTOK * 64 + 255) / 256, 256>>>(
        mask, rel_table, rel_index, combbuf);
    {
        const size_t n4 = (size_t)MROWS * DIMC / 4;
        prep_x_kernel<<<(unsigned)((n4 + 255) / 256), 256>>>(x, x16, n4);
    }

    {   // QKV GEMM (fp16 2-MMA) -> bf16 hi/lo qkv
        dim3 grid(QKVN / 128, MROWS / 128);  // (9, 1568)
        mma_gemm<true, true><<<grid, 256, GEMM_SMEM_BYTES>>>(
            x16, wh, wl, qkv_b, nullptr, qh, ql, MROWS, QKVN, DIMC);
    }

    attn_mma_kernel<<<BWIN * 3, 128, ATTN_SMEM_BYTES>>>(qh, ql, combbuf, a16);

    {   // proj GEMM (fp16 2-MMA) -> fp32 out
        dim3 grid(DIMC / 128, MROWS / 128);  // (3, 1568)
        mma_gemm<false, false><<<grid, 256, GEMM_SMEM_BYTES>>>(
            a16, wh + proj_off, wl + proj_off, proj_b, out,
            nullptr, nullptr, MROWS, DIMC, DIMC);
    }
}

// round 13
// speedup vs baseline: 1.8827x; 1.1315x over previous
#include <cuda_runtime.h>
#include <cuda_bf16.h>
#include <cuda_fp16.h>
#include <cstdint>
#include <cstddef>

#define DIMC   384
#define HEADS  12
#define HD     32
#define NTOK   49
#define BWIN   4096
#define NWIN   256
#define MROWS  (BWIN * NTOK)
#define QKVN   (3 * DIMC)
#define QSCALE 0.17677669529663687f

__device__ __half g_q16[(size_t)MROWS * QKVN];         // qkv fp16 (q pre-scaled)
__device__ __half g_x16[(size_t)MROWS * DIMC];         // x as fp16
__device__ __half g_a16[(size_t)MROWS * DIMC];         // attn out as fp16
__device__ __half g_wh[(size_t)(QKVN + DIMC) * DIMC];  // W^T fp16 hi
__device__ __half g_wl[(size_t)(QKVN + DIMC) * DIMC];  // W^T fp16 lo
__device__ float g_comb[(size_t)NWIN * HEADS * NTOK * 64 + 4096];

__device__ __forceinline__ uint32_t smem_u32(const void* p) {
    uint32_t a;
    asm("{ .reg .u64 t; cvta.to.shared.u64 t, %1; cvt.u32.u64 %0, t; }"
        : "=r"(a) : "l"(p));
    return a;
}
__device__ __forceinline__ uint32_t sw128(uint32_t off) {
    return off ^ ((off >> 3) & 0x70);
}
__device__ __forceinline__ void ldsm4(uint32_t (&r)[4], uint32_t addr) {
    asm volatile("ldmatrix.sync.aligned.m8n8.x4.shared.b16 {%0,%1,%2,%3}, [%4];"
        : "=r"(r[0]), "=r"(r[1]), "=r"(r[2]), "=r"(r[3]) : "r"(addr));
}
__device__ __forceinline__ void ldsm4t(uint32_t (&r)[4], uint32_t addr) {
    asm volatile("ldmatrix.sync.aligned.m8n8.x4.trans.shared.b16 {%0,%1,%2,%3}, [%4];"
        : "=r"(r[0]), "=r"(r[1]), "=r"(r[2]), "=r"(r[3]) : "r"(addr));
}
__device__ __forceinline__ void mma_f16(float (&d)[4], const uint32_t (&a)[4],
                                        uint32_t b0, uint32_t b1) {
    asm volatile(
        "mma.sync.aligned.m16n8k16.row.col.f32.f16.f16.f32 "
        "{%0,%1,%2,%3}, {%4,%5,%6,%7}, {%8,%9}, {%0,%1,%2,%3};"
        : "+f"(d[0]), "+f"(d[1]), "+f"(d[2]), "+f"(d[3])
        : "r"(a[0]), "r"(a[1]), "r"(a[2]), "r"(a[3]), "r"(b0), "r"(b1));
}
__device__ __forceinline__ void cp16(uint32_t dst, const void* src) {
    asm volatile("cp.async.cg.shared.global [%0], [%1], 16;"
                 :: "r"(dst), "l"(src));
}
#define CP_COMMIT() asm volatile("cp.async.commit_group;" ::: "memory")
#define CP_WAIT1()  asm volatile("cp.async.wait_group 1;" ::: "memory")
#define CP_WAIT0()  asm volatile("cp.async.wait_group 0;" ::: "memory")

// fp16 hi/lo split (for P in attention)
__device__ __forceinline__ void split2h(float x, float y, uint32_t& h, uint32_t& l) {
    __half2 hp = __floats2half2_rn(x, y);
    __half2 lp = __floats2half2_rn(x - __low2float(hp), y - __high2float(hp));
    h = *(uint32_t*)&hp;
    l = *(uint32_t*)&lp;
}

// ------------------------------- prep kernels -------------------------------
__global__ void prep_w_kernel(const float* __restrict__ W,
                              __half* __restrict__ hi,
                              __half* __restrict__ lo, int K, int N) {
    int idx = blockIdx.x * blockDim.x + threadIdx.x;
    if (idx >= N * K) return;
    int n = idx / K, k = idx % K;
    float x = W[(size_t)k * N + n];
    __half h = __float2half_rn(x);
    hi[idx] = h;
    lo[idx] = __float2half_rn(x - __half2float(h));
}

__global__ void prep_x_kernel(const float* __restrict__ x,
                              __half* __restrict__ x16, size_t n4) {
    size_t i = (size_t)blockIdx.x * blockDim.x + threadIdx.x;
    if (i >= n4) return;
    float4 xv = ((const float4*)x)[i];
    __half2 a = __floats2half2_rn(xv.x, xv.y);
    __half2 b = __floats2half2_rn(xv.z, xv.w);
    ((uint2*)x16)[i] = make_uint2(*(uint32_t*)&a, *(uint32_t*)&b);
}

// comb[w][h][R][C64] = mask[w][R][C] + clip(bias,+-5); 0 for C>=49
__global__ void prep_comb_kernel(const float* __restrict__ mask,
                                 const float* __restrict__ table,
                                 const int* __restrict__ idx,
                                 float* __restrict__ out) {
    int e = blockIdx.x * blockDim.x + threadIdx.x;
    if (e >= NWIN * HEADS * NTOK * 64) return;
    int C = e & 63, R = (e >> 6) % NTOK;
    int wh = e / (NTOK * 64);
    int w = wh / HEADS, h = wh % HEADS;
    float v = 0.f;
    if (C < NTOK) {
        float b = table[idx[R * NTOK + C] * HEADS + h];
        v = mask[(size_t)w * NTOK * NTOK + R * NTOK + C]
          + fminf(fmaxf(b, -5.f), 5.f);
    }
    out[e] = v;
}

// ---- fp16 GEMM: C = A @ Wt^T + bias. A single fp16, Wt fp16 hi/lo (2 MMAs).
// BM=BN=128, BK=64, 3 stages; stage = A 16KB + Bh 16KB + Bl 16KB = 48KB.
#define GEMM_SMEM_BYTES (3 * 49152)

template <bool QKV, bool H16OUT>
__global__ __launch_bounds__(256, 1) void mma_gemm(
    const __half* __restrict__ A16,
    const __half* __restrict__ Bhi, const __half* __restrict__ Blo,
    const float* __restrict__ bias, float* __restrict__ C,
    __half* __restrict__ C16,
    int M, int N, int K)
{
    extern __shared__ char smem[];
    const uint32_t sb = smem_u32(smem);
    const int tid = threadIdx.x, lane = tid & 31, wid = tid >> 5;
    const int wm = wid & 3, wn = wid >> 2;
    const int bm = blockIdx.y * 128, bn = blockIdx.x * 128;
    const int NCH = K / 64;
    const int crow = tid >> 3, cpos = tid & 7;

    auto cp_stage = [&](int s, int ch) {
        const int k0 = ch * 64;
        const uint32_t st = sb + s * 49152;
        #pragma unroll
        for (int t = 0; t < 4; t++) {
            const int row = t * 32 + crow;
            const uint32_t soff = sw128((uint32_t)(row * 128 + cpos * 16));
            const size_t ga = (size_t)(bm + row) * K + k0 + cpos * 8;
            const size_t gb = (size_t)(bn + row) * K + k0 + cpos * 8;
            cp16(st + soff,         A16 + ga);
            cp16(st + 16384 + soff, Bhi + gb);
            cp16(st + 32768 + soff, Blo + gb);
        }
    };

    float acc[2][8][4] = {};

    auto domma = [&](int s) {
        const uint32_t sA = sb + s * 49152;
        const uint32_t sBh = sA + 16384, sBl = sA + 32768;
        #pragma unroll
        for (int ks = 0; ks < 4; ks++) {
            const int cb = ks * 32 + (lane >> 4) * 16;
            uint32_t af[2][4];
            #pragma unroll
            for (int mt = 0; mt < 2; mt++) {
                const int r = wm * 32 + mt * 16 + (lane & 15);
                ldsm4(af[mt], sA + sw128((uint32_t)(r * 128 + cb)));
            }
            uint32_t bh[4][4], bl[4][4];
            #pragma unroll
            for (int g = 0; g < 4; g++) {
                const int r = wn * 64 + g * 16 + (lane & 15);
                const uint32_t o = sw128((uint32_t)(r * 128 + cb));
                ldsm4(bh[g], sBh + o);
                ldsm4(bl[g], sBl + o);
            }
            #pragma unroll
            for (int mt = 0; mt < 2; mt++)
                #pragma unroll
                for (int nt = 0; nt < 8; nt++) {
                    const int g = nt >> 1, o = nt & 1;
                    mma_f16(acc[mt][nt], af[mt], bh[g][o], bh[g][o + 2]);
                    mma_f16(acc[mt][nt], af[mt], bl[g][o], bl[g][o + 2]);
                }
        }
    };

    cp_stage(0, 0); CP_COMMIT();
    cp_stage(1, 1); CP_COMMIT();
    for (int ch = 0; ch < NCH; ch++) {
        const int s = ch % 3;
        CP_WAIT1();
        __syncthreads();
        if (ch + 2 < NCH) cp_stage((ch + 2) % 3, ch + 2);
        CP_COMMIT();
        domma(s);
    }

    const float qs = (QKV && bn < DIMC) ? QSCALE : 1.0f;
    #pragma unroll
    for (int mt = 0; mt < 2; mt++) {
        const int r0 = bm + wm * 32 + mt * 16 + (lane >> 2);
        #pragma unroll
        for (int nt = 0; nt < 8; nt++) {
            const int c0 = bn + wn * 64 + nt * 8 + (lane & 3) * 2;
            const float2 bv = *(const float2*)(bias + c0);
            float x0 = (acc[mt][nt][0] + bv.x) * qs;
            float y0 = (acc[mt][nt][1] + bv.y) * qs;
            float x1 = (acc[mt][nt][2] + bv.x) * qs;
            float y1 = (acc[mt][nt][3] + bv.y) * qs;
            if (H16OUT) {   // single fp16 for attention
                __half2 h0 = __floats2half2_rn(x0, y0);
                __half2 h1 = __floats2half2_rn(x1, y1);
                *(uint32_t*)(C16 + (size_t)r0 * N + c0)       = *(uint32_t*)&h0;
                *(uint32_t*)(C16 + (size_t)(r0 + 8) * N + c0) = *(uint32_t*)&h1;
            } else {
                *(float2*)(C + (size_t)r0 * N + c0)       = make_float2(x0, y0);
                *(float2*)(C + (size_t)(r0 + 8) * N + c0) = make_float2(x1, y1);
            }
        }
    }
}

// ---------------- Attention: fp16 single q/k/v; S 1-MMA, P(hi/lo)·V 2-MMA ---
// CTA = 128 thr = 4 warps = 4 heads of one window (3 CTAs/window).
// smem: 3 blocks (Q K V) x 16KB; block = 2 sub-tiles of 8KB,
// sub-tile = 64 rows x 128B ([head 2t | head 2t+1] 64B each), SW128.
#define ATTN_SMEM_BYTES (3 * 16384)

__global__ __launch_bounds__(128, 2) void attn_mma_kernel(
    const __half* __restrict__ q16_g,
    const float* __restrict__ comb, __half* __restrict__ o16)
{
    extern __shared__ char smem[];
    const uint32_t sb = smem_u32(smem);
    const int tid = threadIdx.x, lane = tid & 31, wid = tid >> 5;
    const int b = blockIdx.x / 3, hg = blockIdx.x % 3;
    const int h = hg * 4 + wid;

    // zero pad rows 49..63 of all 6 sub-tiles
    for (int i = tid; i < 6 * 15 * 8; i += 128) {
        const int t = i / 120, rr = 49 + (i % 120) / 8, q4 = i % 8;
        *(uint4*)(smem + t * 8192 + sw128((uint32_t)(rr * 128 + q4 * 16))) =
            make_uint4(0, 0, 0, 0);
    }
    // stage q/k/v: 49 rows x 3 matrices x 16 chunks of 16B
    {
        const size_t rowbase = (size_t)b * NTOK * QKVN;
        for (int i = tid; i < NTOK * 48; i += 128) {
            const int n = i / 48, rem = i % 48;
            const int mat = rem >> 4, ck = rem & 15;
            const __half* src = q16_g + rowbase + (size_t)n * QKVN
                              + mat * DIMC + hg * 128 + ck * 8;
            const uint32_t dst = sb + mat * 16384 + (ck >> 3) * 8192
                               + sw128((uint32_t)(n * 128 + (ck & 7) * 16));
            cp16(dst, src);
        }
    }
    CP_COMMIT(); CP_WAIT0();
    __syncthreads();

    const int t = wid >> 1, th = wid & 1;
    const uint32_t Qm = sb + t * 8192;
    const uint32_t Km = Qm + 16384, Vm = Qm + 32768;

    // S = Q @ K^T (64x56, k=32), 1 MMA per tile
    float acc[4][7][4] = {};
    #pragma unroll
    for (int ks = 0; ks < 2; ks++) {
        const uint32_t qb = (uint32_t)(th * 64 + (2 * ks + (lane >> 4)) * 16);
        uint32_t qf[4][4];
        #pragma unroll
        for (int mt = 0; mt < 4; mt++) {
            const int r = mt * 16 + (lane & 15);
            ldsm4(qf[mt], Qm + sw128((uint32_t)(r * 128) + qb));
        }
        #pragma unroll
        for (int g = 0; g < 4; g++) {
            const int rk = g * 16 + (lane & 15);
            uint32_t kf[4];
            ldsm4(kf, Km + sw128((uint32_t)(rk * 128) + qb));
            #pragma unroll
            for (int o = 0; o < 2; o++) {
                const int nt = g * 2 + o;
                if (nt == 7) continue;
                #pragma unroll
                for (int mt = 0; mt < 4; mt++)
                    mma_f16(acc[mt][nt], qf[mt], kf[o], kf[o + 2]);
            }
        }
    }

    // + comb, clip +-10, mask padded cols
    const float* cw = comb + ((size_t)(b & (NWIN - 1)) * HEADS + h) * (NTOK * 64);
    #pragma unroll
    for (int mt = 0; mt < 4; mt++)
        #pragma unroll
        for (int nt = 0; nt < 7; nt++) {
            const int C0 = nt * 8 + 2 * (lane & 3);
            #pragma unroll
            for (int rh = 0; rh < 2; rh++) {
                const int R = mt * 16 + (lane >> 2) + rh * 8;
                const float2 cb = *(const float2*)(cw + R * 64 + C0);
                float s0 = fminf(fmaxf(acc[mt][nt][rh*2]   + cb.x, -10.f), 10.f);
                float s1 = fminf(fmaxf(acc[mt][nt][rh*2+1] + cb.y, -10.f), 10.f);
                if (nt == 6) {
                    if (C0 >= NTOK)     s0 = -1e30f;
                    if (C0 + 1 >= NTOK) s1 = -1e30f;
                }
                acc[mt][nt][rh*2]   = s0;
                acc[mt][nt][rh*2+1] = s1;
            }
        }

    // register softmax (row on 4 lanes)
    #pragma unroll
    for (int mt = 0; mt < 4; mt++)
        #pragma unroll
        for (int rh = 0; rh < 2; rh++) {
            float mx = -1e30f;
            #pragma unroll
            for (int nt = 0; nt < 7; nt++)
                mx = fmaxf(mx, fmaxf(acc[mt][nt][rh*2], acc[mt][nt][rh*2+1]));
            mx = fmaxf(mx, __shfl_xor_sync(0xffffffffu, mx, 1));
            mx = fmaxf(mx, __shfl_xor_sync(0xffffffffu, mx, 2));
            float sum = 0.f;
            #pragma unroll
            for (int nt = 0; nt < 7; nt++) {
                float e0 = __expf(acc[mt][nt][rh*2]   - mx);
                float e1 = __expf(acc[mt][nt][rh*2+1] - mx);
                acc[mt][nt][rh*2] = e0; acc[mt][nt][rh*2+1] = e1;
                sum += e0 + e1;
            }
            sum += __shfl_xor_sync(0xffffffffu, sum, 1);
            sum += __shfl_xor_sync(0xffffffffu, sum, 2);
            const float inv = 1.f / sum;
            #pragma unroll
            for (int nt = 0; nt < 7; nt++) {
                acc[mt][nt][rh*2] *= inv; acc[mt][nt][rh*2+1] *= inv;
            }
        }

    // out = P @ V (k=64 tokens, n=32 d): P hi/lo fp16 x V single fp16
    float oacc[4][4][4] = {};
    #pragma unroll
    for (int kk = 0; kk < 4; kk++) {
        uint32_t vf[2][4];
        #pragma unroll
        for (int dp = 0; dp < 2; dp++) {
            const int rm = kk * 16 + (lane & 15);
            const uint32_t vb = (uint32_t)(th * 64 + dp * 32 + (lane >> 4) * 16);
            ldsm4t(vf[dp], Vm + sw128((uint32_t)(rm * 128) + vb));
        }
        const int nta = kk * 2, ntb = kk * 2 + 1;
        #pragma unroll
        for (int mt = 0; mt < 4; mt++) {
            uint32_t ph[4], pl[4];
            split2h(acc[mt][nta][0], acc[mt][nta][1], ph[0], pl[0]);
            split2h(acc[mt][nta][2], acc[mt][nta][3], ph[1], pl[1]);
            if (ntb < 7) {
                split2h(acc[mt][ntb][0], acc[mt][ntb][1], ph[2], pl[2]);
                split2h(acc[mt][ntb][2], acc[mt][ntb][3], ph[3], pl[3]);
            } else {
                ph[2] = ph[3] = pl[2] = pl[3] = 0u;
            }
            #pragma unroll
            for (int dp = 0; dp < 2; dp++)
                #pragma unroll
                for (int o = 0; o < 2; o++) {
                    const int dt = dp * 2 + o;
                    mma_f16(oacc[mt][dt], ph, vf[dp][2*o], vf[dp][2*o+1]);
                    mma_f16(oacc[mt][dt], pl, vf[dp][2*o], vf[dp][2*o+1]);
                }
        }
    }

    // store single fp16 for proj GEMM
    const size_t ob = (size_t)b * NTOK * DIMC + h * HD;
    #pragma unroll
    for (int mt = 0; mt < 4; mt++)
        #pragma unroll
        for (int rh = 0; rh < 2; rh++) {
            const int R = mt * 16 + (lane >> 2) + rh * 8;
            if (R < NTOK) {
                #pragma unroll
                for (int dt = 0; dt < 4; dt++) {
                    __half2 hv = __floats2half2_rn(oacc[mt][dt][rh*2],
                                                   oacc[mt][dt][rh*2+1]);
                    const size_t o = ob + (size_t)R * DIMC + dt * 8 + 2 * (lane & 3);
                    *(uint32_t*)(o16 + o) = *(uint32_t*)&hv;
                }
            }
        }
}

// ---------------------------------------------------------------------------
extern "C" void kernel_launch(void* const* d_in, const int* in_sizes, int n_in,
                              void* d_out, int out_size)
{
    const float* x         = (const float*)d_in[0];
    const float* mask      = (const float*)d_in[1];
    const float* qkv_w     = (const float*)d_in[2];
    const float* qkv_b     = (const float*)d_in[3];
    const float* proj_w    = (const float*)d_in[4];
    const float* proj_b    = (const float*)d_in[5];
    const float* rel_table = (const float*)d_in[6];
    const int*   rel_index = (const int*)d_in[7];
    float*       out       = (float*)d_out;

    float* combbuf = nullptr;
    __half *q16, *x16, *a16, *wh, *wl;
    cudaGetSymbolAddress((void**)&combbuf, g_comb);
    cudaGetSymbolAddress((void**)&q16, g_q16);
    cudaGetSymbolAddress((void**)&x16, g_x16);
    cudaGetSymbolAddress((void**)&a16, g_a16);
    cudaGetSymbolAddress((void**)&wh, g_wh);
    cudaGetSymbolAddress((void**)&wl, g_wl);

    static int _once = []() {
        cudaFuncSetAttribute(mma_gemm<true, true>,
            cudaFuncAttributeMaxDynamicSharedMemorySize, GEMM_SMEM_BYTES);
        cudaFuncSetAttribute(mma_gemm<false, false>,
            cudaFuncAttributeMaxDynamicSharedMemorySize, GEMM_SMEM_BYTES);
        cudaFuncSetAttribute(attn_mma_kernel,
            cudaFuncAttributeMaxDynamicSharedMemorySize, ATTN_SMEM_BYTES);
        return 0;
    }();
    (void)_once;

    const size_t proj_off = (size_t)QKVN * DIMC;

    prep_w_kernel<<<(QKVN * DIMC + 255) / 256, 256>>>(qkv_w, wh, wl,
                                                      DIMC, QKVN);
    prep_w_kernel<<<(DIMC * DIMC + 255) / 256, 256>>>(
        proj_w, wh + proj_off, wl + proj_off, DIMC, DIMC);
    prep_comb_kernel<<<(NWIN * HEADS * NTOK * 64 + 255) / 256, 256>>>(
        mask, rel_table, rel_index, combbuf);
    {
        const size_t n4 = (size_t)MROWS * DIMC / 4;
        prep_x_kernel<<<(unsigned)((n4 + 255) / 256), 256>>>(x, x16, n4);
    }

    {   // QKV GEMM (fp16 2-MMA) -> single fp16 qkv
        dim3 grid(QKVN / 128, MROWS / 128);  // (9, 1568)
        mma_gemm<true, true><<<grid, 256, GEMM_SMEM_BYTES>>>(
            x16, wh, wl, qkv_b, nullptr, q16, MROWS, QKVN, DIMC);
    }

    attn_mma_kernel<<<BWIN * 3, 128, ATTN_SMEM_BYTES>>>(q16, combbuf, a16);

    {   // proj GEMM (fp16 2-MMA) -> fp32 out
        dim3 grid(DIMC / 128, MROWS / 128);  // (3, 1568)
        mma_gemm<false, false><<<grid, 256, GEMM_SMEM_BYTES>>>(
            a16, wh + proj_off, wl + proj_off, proj_b, out,
            nullptr, MROWS, DIMC, DIMC);
    }
}

// round 14
// speedup vs baseline: 2.9182x; 1.5501x over previous
#include <cuda_runtime.h>
#include <cuda_bf16.h>
#include <cuda_fp16.h>
#include <cstdint>
#include <cstddef>

#define DIMC   384
#define HEADS  12
#define HD     32
#define NTOK   49
#define BWIN   4096
#define NWIN   256
#define MROWS  (BWIN * NTOK)
#define QKVN   (3 * DIMC)
#define QSCALE 0.17677669529663687f

__device__ __half g_q16[(size_t)MROWS * QKVN];         // qkv fp16 (q pre-scaled)
__device__ __half g_x16[(size_t)MROWS * DIMC];         // x as fp16
__device__ __half g_a16[(size_t)MROWS * DIMC];         // attn out as fp16
__device__ __half g_w16[(size_t)(QKVN + DIMC) * DIMC]; // W^T fp16
__device__ float g_comb[(size_t)NWIN * HEADS * NTOK * 64 + 4096];

__device__ __forceinline__ uint32_t smem_u32(const void* p) {
    uint32_t a;
    asm("{ .reg .u64 t; cvta.to.shared.u64 t, %1; cvt.u32.u64 %0, t; }"
        : "=r"(a) : "l"(p));
    return a;
}
__device__ __forceinline__ uint32_t sw128(uint32_t off) {
    return off ^ ((off >> 3) & 0x70);
}
__device__ __forceinline__ void ldsm4(uint32_t (&r)[4], uint32_t addr) {
    asm volatile("ldmatrix.sync.aligned.m8n8.x4.shared.b16 {%0,%1,%2,%3}, [%4];"
        : "=r"(r[0]), "=r"(r[1]), "=r"(r[2]), "=r"(r[3]) : "r"(addr));
}
__device__ __forceinline__ void ldsm4t(uint32_t (&r)[4], uint32_t addr) {
    asm volatile("ldmatrix.sync.aligned.m8n8.x4.trans.shared.b16 {%0,%1,%2,%3}, [%4];"
        : "=r"(r[0]), "=r"(r[1]), "=r"(r[2]), "=r"(r[3]) : "r"(addr));
}
__device__ __forceinline__ void mma_f16(float (&d)[4], const uint32_t (&a)[4],
                                        uint32_t b0, uint32_t b1) {
    asm volatile(
        "mma.sync.aligned.m16n8k16.row.col.f32.f16.f16.f32 "
        "{%0,%1,%2,%3}, {%4,%5,%6,%7}, {%8,%9}, {%0,%1,%2,%3};"
        : "+f"(d[0]), "+f"(d[1]), "+f"(d[2]), "+f"(d[3])
        : "r"(a[0]), "r"(a[1]), "r"(a[2]), "r"(a[3]), "r"(b0), "r"(b1));
}
__device__ __forceinline__ void cp16(uint32_t dst, const void* src) {
    asm volatile("cp.async.cg.shared.global [%0], [%1], 16;"
                 :: "r"(dst), "l"(src));
}
#define CP_COMMIT() asm volatile("cp.async.commit_group;" ::: "memory")
#define CP_WAIT1()  asm volatile("cp.async.wait_group 1;" ::: "memory")
#define CP_WAIT0()  asm volatile("cp.async.wait_group 0;" ::: "memory")

// fp16 hi/lo split (for P in attention)
__device__ __forceinline__ void split2h(float x, float y, uint32_t& h, uint32_t& l) {
    __half2 hp = __floats2half2_rn(x, y);
    __half2 lp = __floats2half2_rn(x - __low2float(hp), y - __high2float(hp));
    h = *(uint32_t*)&hp;
    l = *(uint32_t*)&lp;
}

// ------------------------------- prep kernels -------------------------------
__global__ void prep_w_kernel(const float* __restrict__ W,
                              __half* __restrict__ w16, int K, int N) {
    int idx = blockIdx.x * blockDim.x + threadIdx.x;
    if (idx >= N * K) return;
    int n = idx / K, k = idx % K;
    w16[idx] = __float2half_rn(W[(size_t)k * N + n]);
}

__global__ void prep_x_kernel(const float* __restrict__ x,
                              __half* __restrict__ x16, size_t n4) {
    size_t i = (size_t)blockIdx.x * blockDim.x + threadIdx.x;
    if (i >= n4) return;
    float4 xv = ((const float4*)x)[i];
    __half2 a = __floats2half2_rn(xv.x, xv.y);
    __half2 b = __floats2half2_rn(xv.z, xv.w);
    ((uint2*)x16)[i] = make_uint2(*(uint32_t*)&a, *(uint32_t*)&b);
}

// comb[w][h][R][C64] = mask[w][R][C] + clip(bias,+-5); 0 for C>=49
__global__ void prep_comb_kernel(const float* __restrict__ mask,
                                 const float* __restrict__ table,
                                 const int* __restrict__ idx,
                                 float* __restrict__ out) {
    int e = blockIdx.x * blockDim.x + threadIdx.x;
    if (e >= NWIN * HEADS * NTOK * 64) return;
    int C = e & 63, R = (e >> 6) % NTOK;
    int wh = e / (NTOK * 64);
    int w = wh / HEADS, h = wh % HEADS;
    float v = 0.f;
    if (C < NTOK) {
        float b = table[idx[R * NTOK + C] * HEADS + h];
        v = mask[(size_t)w * NTOK * NTOK + R * NTOK + C]
          + fminf(fmaxf(b, -5.f), 5.f);
    }
    out[e] = v;
}

// ---- fp16 GEMM: C = A @ Wt^T + bias. Single fp16 A and W (1 MMA per tile).
// BM=BN=128, BK=64, 3 stages; stage = A 16KB + B 16KB = 32KB -> 2 CTAs/SM.
#define GEMM_SMEM_BYTES (3 * 32768)

template <bool QKV, bool H16OUT>
__global__ __launch_bounds__(256, 2) void mma_gemm(
    const __half* __restrict__ A16, const __half* __restrict__ B16,
    const float* __restrict__ bias, float* __restrict__ C,
    __half* __restrict__ C16,
    int M, int N, int K)
{
    extern __shared__ char smem[];
    const uint32_t sb = smem_u32(smem);
    const int tid = threadIdx.x, lane = tid & 31, wid = tid >> 5;
    const int wm = wid & 3, wn = wid >> 2;
    const int bm = blockIdx.y * 128, bn = blockIdx.x * 128;
    const int NCH = K / 64;
    const int crow = tid >> 3, cpos = tid & 7;

    auto cp_stage = [&](int s, int ch) {
        const int k0 = ch * 64;
        const uint32_t st = sb + s * 32768;
        #pragma unroll
        for (int t = 0; t < 4; t++) {
            const int row = t * 32 + crow;
            const uint32_t soff = sw128((uint32_t)(row * 128 + cpos * 16));
            const size_t ga = (size_t)(bm + row) * K + k0 + cpos * 8;
            const size_t gb = (size_t)(bn + row) * K + k0 + cpos * 8;
            cp16(st + soff,         A16 + ga);
            cp16(st + 16384 + soff, B16 + gb);
        }
    };

    float acc[2][8][4] = {};

    auto domma = [&](int s) {
        const uint32_t sA = sb + s * 32768;
        const uint32_t sB = sA + 16384;
        #pragma unroll
        for (int ks = 0; ks < 4; ks++) {
            const int cb = ks * 32 + (lane >> 4) * 16;
            uint32_t af[2][4];
            #pragma unroll
            for (int mt = 0; mt < 2; mt++) {
                const int r = wm * 32 + mt * 16 + (lane & 15);
                ldsm4(af[mt], sA + sw128((uint32_t)(r * 128 + cb)));
            }
            uint32_t bf[4][4];
            #pragma unroll
            for (int g = 0; g < 4; g++) {
                const int r = wn * 64 + g * 16 + (lane & 15);
                ldsm4(bf[g], sB + sw128((uint32_t)(r * 128 + cb)));
            }
            #pragma unroll
            for (int mt = 0; mt < 2; mt++)
                #pragma unroll
                for (int nt = 0; nt < 8; nt++) {
                    const int g = nt >> 1, o = nt & 1;
                    mma_f16(acc[mt][nt], af[mt], bf[g][o], bf[g][o + 2]);
                }
        }
    };

    cp_stage(0, 0); CP_COMMIT();
    cp_stage(1, 1); CP_COMMIT();
    for (int ch = 0; ch < NCH; ch++) {
        const int s = ch % 3;
        CP_WAIT1();
        __syncthreads();
        if (ch + 2 < NCH) cp_stage((ch + 2) % 3, ch + 2);
        CP_COMMIT();
        domma(s);
    }

    const float qs = (QKV && bn < DIMC) ? QSCALE : 1.0f;
    #pragma unroll
    for (int mt = 0; mt < 2; mt++) {
        const int r0 = bm + wm * 32 + mt * 16 + (lane >> 2);
        #pragma unroll
        for (int nt = 0; nt < 8; nt++) {
            const int c0 = bn + wn * 64 + nt * 8 + (lane & 3) * 2;
            const float2 bv = *(const float2*)(bias + c0);
            float x0 = (acc[mt][nt][0] + bv.x) * qs;
            float y0 = (acc[mt][nt][1] + bv.y) * qs;
            float x1 = (acc[mt][nt][2] + bv.x) * qs;
            float y1 = (acc[mt][nt][3] + bv.y) * qs;
            if (H16OUT) {
                __half2 h0 = __floats2half2_rn(x0, y0);
                __half2 h1 = __floats2half2_rn(x1, y1);
                *(uint32_t*)(C16 + (size_t)r0 * N + c0)       = *(uint32_t*)&h0;
                *(uint32_t*)(C16 + (size_t)(r0 + 8) * N + c0) = *(uint32_t*)&h1;
            } else {
                *(float2*)(C + (size_t)r0 * N + c0)       = make_float2(x0, y0);
                *(float2*)(C + (size_t)(r0 + 8) * N + c0) = make_float2(x1, y1);
            }
        }
    }
}

// ---------------- Attention (unchanged from R13) ----------------------------
#define ATTN_SMEM_BYTES (3 * 16384)

__global__ __launch_bounds__(128, 2) void attn_mma_kernel(
    const __half* __restrict__ q16_g,
    const float* __restrict__ comb, __half* __restrict__ o16)
{
    extern __shared__ char smem[];
    const uint32_t sb = smem_u32(smem);
    const int tid = threadIdx.x, lane = tid & 31, wid = tid >> 5;
    const int b = blockIdx.x / 3, hg = blockIdx.x % 3;
    const int h = hg * 4 + wid;

    for (int i = tid; i < 6 * 15 * 8; i += 128) {
        const int t = i / 120, rr = 49 + (i % 120) / 8, q4 = i % 8;
        *(uint4*)(smem + t * 8192 + sw128((uint32_t)(rr * 128 + q4 * 16))) =
            make_uint4(0, 0, 0, 0);
    }
    {
        const size_t rowbase = (size_t)b * NTOK * QKVN;
        for (int i = tid; i < NTOK * 48; i += 128) {
            const int n = i / 48, rem = i % 48;
            const int mat = rem >> 4, ck = rem & 15;
            const __half* src = q16_g + rowbase + (size_t)n * QKVN
                              + mat * DIMC + hg * 128 + ck * 8;
            const uint32_t dst = sb + mat * 16384 + (ck >> 3) * 8192
                               + sw128((uint32_t)(n * 128 + (ck & 7) * 16));
            cp16(dst, src);
        }
    }
    CP_COMMIT(); CP_WAIT0();
    __syncthreads();

    const int t = wid >> 1, th = wid & 1;
    const uint32_t Qm = sb + t * 8192;
    const uint32_t Km = Qm + 16384, Vm = Qm + 32768;

    float acc[4][7][4] = {};
    #pragma unroll
    for (int ks = 0; ks < 2; ks++) {
        const uint32_t qb = (uint32_t)(th * 64 + (2 * ks + (lane >> 4)) * 16);
        uint32_t qf[4][4];
        #pragma unroll
        for (int mt = 0; mt < 4; mt++) {
            const int r = mt * 16 + (lane & 15);
            ldsm4(qf[mt], Qm + sw128((uint32_t)(r * 128) + qb));
        }
        #pragma unroll
        for (int g = 0; g < 4; g++) {
            const int rk = g * 16 + (lane & 15);
            uint32_t kf[4];
            ldsm4(kf, Km + sw128((uint32_t)(rk * 128) + qb));
            #pragma unroll
            for (int o = 0; o < 2; o++) {
                const int nt = g * 2 + o;
                if (nt == 7) continue;
                #pragma unroll
                for (int mt = 0; mt < 4; mt++)
                    mma_f16(acc[mt][nt], qf[mt], kf[o], kf[o + 2]);
            }
        }
    }

    const float* cw = comb + ((size_t)(b & (NWIN - 1)) * HEADS + h) * (NTOK * 64);
    #pragma unroll
    for (int mt = 0; mt < 4; mt++)
        #pragma unroll
        for (int nt = 0; nt < 7; nt++) {
            const int C0 = nt * 8 + 2 * (lane & 3);
            #pragma unroll
            for (int rh = 0; rh < 2; rh++) {
                const int R = mt * 16 + (lane >> 2) + rh * 8;
                const float2 cb = *(const float2*)(cw + R * 64 + C0);
                float s0 = fminf(fmaxf(acc[mt][nt][rh*2]   + cb.x, -10.f), 10.f);
                float s1 = fminf(fmaxf(acc[mt][nt][rh*2+1] + cb.y, -10.f), 10.f);
                if (nt == 6) {
                    if (C0 >= NTOK)     s0 = -1e30f;
                    if (C0 + 1 >= NTOK) s1 = -1e30f;
                }
                acc[mt][nt][rh*2]   = s0;
                acc[mt][nt][rh*2+1] = s1;
            }
        }

    #pragma unroll
    for (int mt = 0; mt < 4; mt++)
        #pragma unroll
        for (int rh = 0; rh < 2; rh++) {
            float mx = -1e30f;
            #pragma unroll
            for (int nt = 0; nt < 7; nt++)
                mx = fmaxf(mx, fmaxf(acc[mt][nt][rh*2], acc[mt][nt][rh*2+1]));
            mx = fmaxf(mx, __shfl_xor_sync(0xffffffffu, mx, 1));
            mx = fmaxf(mx, __shfl_xor_sync(0xffffffffu, mx, 2));
            float sum = 0.f;
            #pragma unroll
            for (int nt = 0; nt < 7; nt++) {
                float e0 = __expf(acc[mt][nt][rh*2]   - mx);
                float e1 = __expf(acc[mt][nt][rh*2+1] - mx);
                acc[mt][nt][rh*2] = e0; acc[mt][nt][rh*2+1] = e1;
                sum += e0 + e1;
            }
            sum += __shfl_xor_sync(0xffffffffu, sum, 1);
            sum += __shfl_xor_sync(0xffffffffu, sum, 2);
            const float inv = 1.f / sum;
            #pragma unroll
            for (int nt = 0; nt < 7; nt++) {
                acc[mt][nt][rh*2] *= inv; acc[mt][nt][rh*2+1] *= inv;
            }
        }

    float oacc[4][4][4] = {};
    #pragma unroll
    for (int kk = 0; kk < 4; kk++) {
        uint32_t vf[2][4];
        #pragma unroll
        for (int dp = 0; dp < 2; dp++) {
            const int rm = kk * 16 + (lane & 15);
            const uint32_t vb = (uint32_t)(th * 64 + dp * 32 + (lane >> 4) * 16);
            ldsm4t(vf[dp], Vm + sw128((uint32_t)(rm * 128) + vb));
        }
        const int nta = kk * 2, ntb = kk * 2 + 1;
        #pragma unroll
        for (int mt = 0; mt < 4; mt++) {
            uint32_t ph[4], pl[4];
            split2h(acc[mt][nta][0], acc[mt][nta][1], ph[0], pl[0]);
            split2h(acc[mt][nta][2], acc[mt][nta][3], ph[1], pl[1]);
            if (ntb < 7) {
                split2h(acc[mt][ntb][0], acc[mt][ntb][1], ph[2], pl[2]);
                split2h(acc[mt][ntb][2], acc[mt][ntb][3], ph[3], pl[3]);
            } else {
                ph[2] = ph[3] = pl[2] = pl[3] = 0u;
            }
            #pragma unroll
            for (int dp = 0; dp < 2; dp++)
                #pragma unroll
                for (int o = 0; o < 2; o++) {
                    const int dt = dp * 2 + o;
                    mma_f16(oacc[mt][dt], ph, vf[dp][2*o], vf[dp][2*o+1]);
                    mma_f16(oacc[mt][dt], pl, vf[dp][2*o], vf[dp][2*o+1]);
                }
        }
    }

    const size_t ob = (size_t)b * NTOK * DIMC + h * HD;
    #pragma unroll
    for (int mt = 0; mt < 4; mt++)
        #pragma unroll
        for (int rh = 0; rh < 2; rh++) {
            const int R = mt * 16 + (lane >> 2) + rh * 8;
            if (R < NTOK) {
                #pragma unroll
                for (int dt = 0; dt < 4; dt++) {
                    __half2 hv = __floats2half2_rn(oacc[mt][dt][rh*2],
                                                   oacc[mt][dt][rh*2+1]);
                    const size_t o = ob + (size_t)R * DIMC + dt * 8 + 2 * (lane & 3);
                    *(uint32_t*)(o16 + o) = *(uint32_t*)&hv;
                }
            }
        }
}

// ---------------------------------------------------------------------------
extern "C" void kernel_launch(void* const* d_in, const int* in_sizes, int n_in,
                              void* d_out, int out_size)
{
    const float* x         = (const float*)d_in[0];
    const float* mask      = (const float*)d_in[1];
    const float* qkv_w     = (const float*)d_in[2];
    const float* qkv_b     = (const float*)d_in[3];
    const float* proj_w    = (const float*)d_in[4];
    const float* proj_b    = (const float*)d_in[5];
    const float* rel_table = (const float*)d_in[6];
    const int*   rel_index = (const int*)d_in[7];
    float*       out       = (float*)d_out;

    float* combbuf = nullptr;
    __half *q16, *x16, *a16, *w16;
    cudaGetSymbolAddress((void**)&combbuf, g_comb);
    cudaGetSymbolAddress((void**)&q16, g_q16);
    cudaGetSymbolAddress((void**)&x16, g_x16);
    cudaGetSymbolAddress((void**)&a16, g_a16);
    cudaGetSymbolAddress((void**)&w16, g_w16);

    static int _once = []() {
        cudaFuncSetAttribute(mma_gemm<true, true>,
            cudaFuncAttributeMaxDynamicSharedMemorySize, GEMM_SMEM_BYTES);
        cudaFuncSetAttribute(mma_gemm<false, false>,
            cudaFuncAttributeMaxDynamicSharedMemorySize, GEMM_SMEM_BYTES);
        cudaFuncSetAttribute(attn_mma_kernel,
            cudaFuncAttributeMaxDynamicSharedMemorySize, ATTN_SMEM_BYTES);
        return 0;
    }();
    (void)_once;

    const size_t proj_off = (size_t)QKVN * DIMC;

    prep_w_kernel<<<(QKVN * DIMC + 255) / 256, 256>>>(qkv_w, w16, DIMC, QKVN);
    prep_w_kernel<<<(DIMC * DIMC + 255) / 256, 256>>>(
        proj_w, w16 + proj_off, DIMC, DIMC);
    prep_comb_kernel<<<(NWIN * HEADS * NTOK * 64 + 255) / 256, 256>>>(
        mask, rel_table, rel_index, combbuf);
    {
        const size_t n4 = (size_t)MROWS * DIMC / 4;
        prep_x_kernel<<<(unsigned)((n4 + 255) / 256), 256>>>(x, x16, n4);
    }

    {   // QKV GEMM (fp16 1-MMA) -> single fp16 qkv
        dim3 grid(QKVN / 128, MROWS / 128);  // (9, 1568)
        mma_gemm<true, true><<<grid, 256, GEMM_SMEM_BYTES>>>(
            x16, w16, qkv_b, nullptr, q16, MROWS, QKVN, DIMC);
    }

    attn_mma_kernel<<<BWIN * 3, 128, ATTN_SMEM_BYTES>>>(q16, combbuf, a16);

    {   // proj GEMM (fp16 1-MMA) -> fp32 out
        dim3 grid(DIMC / 128, MROWS / 128);  // (3, 1568)
        mma_gemm<false, false><<<grid, 256, GEMM_SMEM_BYTES>>>(
            a16, w16 + proj_off, proj_b, out, nullptr, MROWS, DIMC, DIMC);
    }
}

// round 15
// speedup vs baseline: 2.9824x; 1.0220x over previous
#include <cuda_runtime.h>
#include <cuda_bf16.h>
#include <cuda_fp16.h>
#include <cstdint>
#include <cstddef>

#define DIMC   384
#define HEADS  12
#define HD     32
#define NTOK   49
#define BWIN   4096
#define NWIN   256
#define MROWS  (BWIN * NTOK)
#define QKVN   (3 * DIMC)
#define QSCALE 0.17677669529663687f

__device__ __half g_q16[(size_t)MROWS * QKVN];         // qkv fp16 (q pre-scaled)
__device__ __half g_x16[(size_t)MROWS * DIMC];         // x as fp16
__device__ __half g_a16[(size_t)MROWS * DIMC];         // attn out as fp16
__device__ __half g_w16[(size_t)(QKVN + DIMC) * DIMC]; // W^T fp16
__device__ float g_comb[(size_t)NWIN * HEADS * NTOK * 64 + 4096];

__device__ __forceinline__ uint32_t smem_u32(const void* p) {
    uint32_t a;
    asm("{ .reg .u64 t; cvta.to.shared.u64 t, %1; cvt.u32.u64 %0, t; }"
        : "=r"(a) : "l"(p));
    return a;
}
__device__ __forceinline__ uint32_t sw128(uint32_t off) {
    return off ^ ((off >> 3) & 0x70);
}
__device__ __forceinline__ void ldsm4(uint32_t (&r)[4], uint32_t addr) {
    asm volatile("ldmatrix.sync.aligned.m8n8.x4.shared.b16 {%0,%1,%2,%3}, [%4];"
        : "=r"(r[0]), "=r"(r[1]), "=r"(r[2]), "=r"(r[3]) : "r"(addr));
}
__device__ __forceinline__ void ldsm4t(uint32_t (&r)[4], uint32_t addr) {
    asm volatile("ldmatrix.sync.aligned.m8n8.x4.trans.shared.b16 {%0,%1,%2,%3}, [%4];"
        : "=r"(r[0]), "=r"(r[1]), "=r"(r[2]), "=r"(r[3]) : "r"(addr));
}
__device__ __forceinline__ void mma_f16(float (&d)[4], const uint32_t (&a)[4],
                                        uint32_t b0, uint32_t b1) {
    asm volatile(
        "mma.sync.aligned.m16n8k16.row.col.f32.f16.f16.f32 "
        "{%0,%1,%2,%3}, {%4,%5,%6,%7}, {%8,%9}, {%0,%1,%2,%3};"
        : "+f"(d[0]), "+f"(d[1]), "+f"(d[2]), "+f"(d[3])
        : "r"(a[0]), "r"(a[1]), "r"(a[2]), "r"(a[3]), "r"(b0), "r"(b1));
}
__device__ __forceinline__ void cp16(uint32_t dst, const void* src) {
    asm volatile("cp.async.cg.shared.global [%0], [%1], 16;"
                 :: "r"(dst), "l"(src));
}
#define CP_COMMIT() asm volatile("cp.async.commit_group;" ::: "memory")
#define CP_WAIT1()  asm volatile("cp.async.wait_group 1;" ::: "memory")
#define CP_WAIT0()  asm volatile("cp.async.wait_group 0;" ::: "memory")

// ------------------------------- prep kernels -------------------------------
__global__ void prep_w_kernel(const float* __restrict__ W,
                              __half* __restrict__ w16, int K, int N) {
    int idx = blockIdx.x * blockDim.x + threadIdx.x;
    if (idx >= N * K) return;
    int n = idx / K, k = idx % K;
    w16[idx] = __float2half_rn(W[(size_t)k * N + n]);
}

__global__ void prep_x_kernel(const float* __restrict__ x,
                              __half* __restrict__ x16, size_t n4) {
    size_t i = (size_t)blockIdx.x * blockDim.x + threadIdx.x;
    if (i >= n4) return;
    float4 xv = ((const float4*)x)[i];
    __half2 a = __floats2half2_rn(xv.x, xv.y);
    __half2 b = __floats2half2_rn(xv.z, xv.w);
    ((uint2*)x16)[i] = make_uint2(*(uint32_t*)&a, *(uint32_t*)&b);
}

// comb[w][h][R][C64] = mask[w][R][C] + clip(bias,+-5); 0 for C>=49
__global__ void prep_comb_kernel(const float* __restrict__ mask,
                                 const float* __restrict__ table,
                                 const int* __restrict__ idx,
                                 float* __restrict__ out) {
    int e = blockIdx.x * blockDim.x + threadIdx.x;
    if (e >= NWIN * HEADS * NTOK * 64) return;
    int C = e & 63, R = (e >> 6) % NTOK;
    int wh = e / (NTOK * 64);
    int w = wh / HEADS, h = wh % HEADS;
    float v = 0.f;
    if (C < NTOK) {
        float b = table[idx[R * NTOK + C] * HEADS + h];
        v = mask[(size_t)w * NTOK * NTOK + R * NTOK + C]
          + fminf(fmaxf(b, -5.f), 5.f);
    }
    out[e] = v;
}

// ---- fp16 GEMM (R14 config): C = A @ Wt^T + bias. 1 MMA per tile.
// BM=BN=128, BK=64, 3 stages; stage = A 16KB + B 16KB = 32KB -> 2 CTAs/SM.
#define GEMM_SMEM_BYTES (3 * 32768)

template <bool QKV, bool H16OUT>
__global__ __launch_bounds__(256, 2) void mma_gemm(
    const __half* __restrict__ A16, const __half* __restrict__ B16,
    const float* __restrict__ bias, float* __restrict__ C,
    __half* __restrict__ C16,
    int M, int N, int K)
{
    extern __shared__ char smem[];
    const uint32_t sb = smem_u32(smem);
    const int tid = threadIdx.x, lane = tid & 31, wid = tid >> 5;
    const int wm = wid & 3, wn = wid >> 2;
    const int bm = blockIdx.y * 128, bn = blockIdx.x * 128;
    const int NCH = K / 64;
    const int crow = tid >> 3, cpos = tid & 7;

    auto cp_stage = [&](int s, int ch) {
        const int k0 = ch * 64;
        const uint32_t st = sb + s * 32768;
        #pragma unroll
        for (int t = 0; t < 4; t++) {
            const int row = t * 32 + crow;
            const uint32_t soff = sw128((uint32_t)(row * 128 + cpos * 16));
            const size_t ga = (size_t)(bm + row) * K + k0 + cpos * 8;
            const size_t gb = (size_t)(bn + row) * K + k0 + cpos * 8;
            cp16(st + soff,         A16 + ga);
            cp16(st + 16384 + soff, B16 + gb);
        }
    };

    float acc[2][8][4] = {};

    auto domma = [&](int s) {
        const uint32_t sA = sb + s * 32768;
        const uint32_t sB = sA + 16384;
        #pragma unroll
        for (int ks = 0; ks < 4; ks++) {
            const int cb = ks * 32 + (lane >> 4) * 16;
            uint32_t af[2][4];
            #pragma unroll
            for (int mt = 0; mt < 2; mt++) {
                const int r = wm * 32 + mt * 16 + (lane & 15);
                ldsm4(af[mt], sA + sw128((uint32_t)(r * 128 + cb)));
            }
            uint32_t bf[4][4];
            #pragma unroll
            for (int g = 0; g < 4; g++) {
                const int r = wn * 64 + g * 16 + (lane & 15);
                ldsm4(bf[g], sB + sw128((uint32_t)(r * 128 + cb)));
            }
            #pragma unroll
            for (int mt = 0; mt < 2; mt++)
                #pragma unroll
                for (int nt = 0; nt < 8; nt++) {
                    const int g = nt >> 1, o = nt & 1;
                    mma_f16(acc[mt][nt], af[mt], bf[g][o], bf[g][o + 2]);
                }
        }
    };

    cp_stage(0, 0); CP_COMMIT();
    cp_stage(1, 1); CP_COMMIT();
    for (int ch = 0; ch < NCH; ch++) {
        const int s = ch % 3;
        CP_WAIT1();
        __syncthreads();
        if (ch + 2 < NCH) cp_stage((ch + 2) % 3, ch + 2);
        CP_COMMIT();
        domma(s);
    }

    const float qs = (QKV && bn < DIMC) ? QSCALE : 1.0f;
    #pragma unroll
    for (int mt = 0; mt < 2; mt++) {
        const int r0 = bm + wm * 32 + mt * 16 + (lane >> 2);
        #pragma unroll
        for (int nt = 0; nt < 8; nt++) {
            const int c0 = bn + wn * 64 + nt * 8 + (lane & 3) * 2;
            const float2 bv = *(const float2*)(bias + c0);
            float x0 = (acc[mt][nt][0] + bv.x) * qs;
            float y0 = (acc[mt][nt][1] + bv.y) * qs;
            float x1 = (acc[mt][nt][2] + bv.x) * qs;
            float y1 = (acc[mt][nt][3] + bv.y) * qs;
            if (H16OUT) {
                __half2 h0 = __floats2half2_rn(x0, y0);
                __half2 h1 = __floats2half2_rn(x1, y1);
                *(uint32_t*)(C16 + (size_t)r0 * N + c0)       = *(uint32_t*)&h0;
                *(uint32_t*)(C16 + (size_t)(r0 + 8) * N + c0) = *(uint32_t*)&h1;
            } else {
                *(float2*)(C + (size_t)r0 * N + c0)       = make_float2(x0, y0);
                *(float2*)(C + (size_t)(r0 + 8) * N + c0) = make_float2(x1, y1);
            }
        }
    }
}

// ---------------- Attention: S 1-MMA, P single fp16 -> P·V 1-MMA ------------
#define ATTN_SMEM_BYTES (3 * 16384)

__global__ __launch_bounds__(128, 2) void attn_mma_kernel(
    const __half* __restrict__ q16_g,
    const float* __restrict__ comb, __half* __restrict__ o16)
{
    extern __shared__ char smem[];
    const uint32_t sb = smem_u32(smem);
    const int tid = threadIdx.x, lane = tid & 31, wid = tid >> 5;
    const int b = blockIdx.x / 3, hg = blockIdx.x % 3;
    const int h = hg * 4 + wid;

    for (int i = tid; i < 6 * 15 * 8; i += 128) {
        const int t = i / 120, rr = 49 + (i % 120) / 8, q4 = i % 8;
        *(uint4*)(smem + t * 8192 + sw128((uint32_t)(rr * 128 + q4 * 16))) =
            make_uint4(0, 0, 0, 0);
    }
    {
        const size_t rowbase = (size_t)b * NTOK * QKVN;
        for (int i = tid; i < NTOK * 48; i += 128) {
            const int n = i / 48, rem = i % 48;
            const int mat = rem >> 4, ck = rem & 15;
            const __half* src = q16_g + rowbase + (size_t)n * QKVN
                              + mat * DIMC + hg * 128 + ck * 8;
            const uint32_t dst = sb + mat * 16384 + (ck >> 3) * 8192
                               + sw128((uint32_t)(n * 128 + (ck & 7) * 16));
            cp16(dst, src);
        }
    }
    CP_COMMIT(); CP_WAIT0();
    __syncthreads();

    const int t = wid >> 1, th = wid & 1;
    const uint32_t Qm = sb + t * 8192;
    const uint32_t Km = Qm + 16384, Vm = Qm + 32768;

    // S = Q @ K^T (64x56, k=32), 1 MMA per tile
    float acc[4][7][4] = {};
    #pragma unroll
    for (int ks = 0; ks < 2; ks++) {
        const uint32_t qb = (uint32_t)(th * 64 + (2 * ks + (lane >> 4)) * 16);
        uint32_t qf[4][4];
        #pragma unroll
        for (int mt = 0; mt < 4; mt++) {
            const int r = mt * 16 + (lane & 15);
            ldsm4(qf[mt], Qm + sw128((uint32_t)(r * 128) + qb));
        }
        #pragma unroll
        for (int g = 0; g < 4; g++) {
            const int rk = g * 16 + (lane & 15);
            uint32_t kf[4];
            ldsm4(kf, Km + sw128((uint32_t)(rk * 128) + qb));
            #pragma unroll
            for (int o = 0; o < 2; o++) {
                const int nt = g * 2 + o;
                if (nt == 7) continue;
                #pragma unroll
                for (int mt = 0; mt < 4; mt++)
                    mma_f16(acc[mt][nt], qf[mt], kf[o], kf[o + 2]);
            }
        }
    }

    // + comb, clip +-10, mask padded cols
    const float* cw = comb + ((size_t)(b & (NWIN - 1)) * HEADS + h) * (NTOK * 64);
    #pragma unroll
    for (int mt = 0; mt < 4; mt++)
        #pragma unroll
        for (int nt = 0; nt < 7; nt++) {
            const int C0 = nt * 8 + 2 * (lane & 3);
            #pragma unroll
            for (int rh = 0; rh < 2; rh++) {
                const int R = mt * 16 + (lane >> 2) + rh * 8;
                const float2 cb = *(const float2*)(cw + R * 64 + C0);
                float s0 = fminf(fmaxf(acc[mt][nt][rh*2]   + cb.x, -10.f), 10.f);
                float s1 = fminf(fmaxf(acc[mt][nt][rh*2+1] + cb.y, -10.f), 10.f);
                if (nt == 6) {
                    if (C0 >= NTOK)     s0 = -1e30f;
                    if (C0 + 1 >= NTOK) s1 = -1e30f;
                }
                acc[mt][nt][rh*2]   = s0;
                acc[mt][nt][rh*2+1] = s1;
            }
        }

    // register softmax (row on 4 lanes)
    #pragma unroll
    for (int mt = 0; mt < 4; mt++)
        #pragma unroll
        for (int rh = 0; rh < 2; rh++) {
            float mx = -1e30f;
            #pragma unroll
            for (int nt = 0; nt < 7; nt++)
                mx = fmaxf(mx, fmaxf(acc[mt][nt][rh*2], acc[mt][nt][rh*2+1]));
            mx = fmaxf(mx, __shfl_xor_sync(0xffffffffu, mx, 1));
            mx = fmaxf(mx, __shfl_xor_sync(0xffffffffu, mx, 2));
            float sum = 0.f;
            #pragma unroll
            for (int nt = 0; nt < 7; nt++) {
                float e0 = __expf(acc[mt][nt][rh*2]   - mx);
                float e1 = __expf(acc[mt][nt][rh*2+1] - mx);
                acc[mt][nt][rh*2] = e0; acc[mt][nt][rh*2+1] = e1;
                sum += e0 + e1;
            }
            sum += __shfl_xor_sync(0xffffffffu, sum, 1);
            sum += __shfl_xor_sync(0xffffffffu, sum, 2);
            const float inv = 1.f / sum;
            #pragma unroll
            for (int nt = 0; nt < 7; nt++) {
                acc[mt][nt][rh*2] *= inv; acc[mt][nt][rh*2+1] *= inv;
            }
        }

    // out = P @ V (k=64 tokens, n=32 d): single fp16 P, 1 MMA per tile
    float oacc[4][4][4] = {};
    #pragma unroll
    for (int kk = 0; kk < 4; kk++) {
        uint32_t vf[2][4];
        #pragma unroll
        for (int dp = 0; dp < 2; dp++) {
            const int rm = kk * 16 + (lane & 15);
            const uint32_t vb = (uint32_t)(th * 64 + dp * 32 + (lane >> 4) * 16);
            ldsm4t(vf[dp], Vm + sw128((uint32_t)(rm * 128) + vb));
        }
        const int nta = kk * 2, ntb = kk * 2 + 1;
        #pragma unroll
        for (int mt = 0; mt < 4; mt++) {
            uint32_t ph[4];
            __half2 p0 = __floats2half2_rn(acc[mt][nta][0], acc[mt][nta][1]);
            __half2 p1 = __floats2half2_rn(acc[mt][nta][2], acc[mt][nta][3]);
            ph[0] = *(uint32_t*)&p0;
            ph[1] = *(uint32_t*)&p1;
            if (ntb < 7) {
                __half2 p2 = __floats2half2_rn(acc[mt][ntb][0], acc[mt][ntb][1]);
                __half2 p3 = __floats2half2_rn(acc[mt][ntb][2], acc[mt][ntb][3]);
                ph[2] = *(uint32_t*)&p2;
                ph[3] = *(uint32_t*)&p3;
            } else {
                ph[2] = ph[3] = 0u;
            }
            #pragma unroll
            for (int dp = 0; dp < 2; dp++)
                #pragma unroll
                for (int o = 0; o < 2; o++) {
                    const int dt = dp * 2 + o;
                    mma_f16(oacc[mt][dt], ph, vf[dp][2*o], vf[dp][2*o+1]);
                }
        }
    }

    // store single fp16 for proj GEMM
    const size_t ob = (size_t)b * NTOK * DIMC + h * HD;
    #pragma unroll
    for (int mt = 0; mt < 4; mt++)
        #pragma unroll
        for (int rh = 0; rh < 2; rh++) {
            const int R = mt * 16 + (lane >> 2) + rh * 8;
            if (R < NTOK) {
                #pragma unroll
                for (int dt = 0; dt < 4; dt++) {
                    __half2 hv = __floats2half2_rn(oacc[mt][dt][rh*2],
                                                   oacc[mt][dt][rh*2+1]);
                    const size_t o = ob + (size_t)R * DIMC + dt * 8 + 2 * (lane & 3);
                    *(uint32_t*)(o16 + o) = *(uint32_t*)&hv;
                }
            }
        }
}

// ---------------------------------------------------------------------------
extern "C" void kernel_launch(void* const* d_in, const int* in_sizes, int n_in,
                              void* d_out, int out_size)
{
    const float* x         = (const float*)d_in[0];
    const float* mask      = (const float*)d_in[1];
    const float* qkv_w     = (const float*)d_in[2];
    const float* qkv_b     = (const float*)d_in[3];
    const float* proj_w    = (const float*)d_in[4];
    const float* proj_b    = (const float*)d_in[5];
    const float* rel_table = (const float*)d_in[6];
    const int*   rel_index = (const int*)d_in[7];
    float*       out       = (float*)d_out;

    float* combbuf = nullptr;
    __half *q16, *x16, *a16, *w16;
    cudaGetSymbolAddress((void**)&combbuf, g_comb);
    cudaGetSymbolAddress((void**)&q16, g_q16);
    cudaGetSymbolAddress((void**)&x16, g_x16);
    cudaGetSymbolAddress((void**)&a16, g_a16);
    cudaGetSymbolAddress((void**)&w16, g_w16);

    static int _once = []() {
        cudaFuncSetAttribute(mma_gemm<true, true>,
            cudaFuncAttributeMaxDynamicSharedMemorySize, GEMM_SMEM_BYTES);
        cudaFuncSetAttribute(mma_gemm<false, false>,
            cudaFuncAttributeMaxDynamicSharedMemorySize, GEMM_SMEM_BYTES);
        cudaFuncSetAttribute(attn_mma_kernel,
            cudaFuncAttributeMaxDynamicSharedMemorySize, ATTN_SMEM_BYTES);
        return 0;
    }();
    (void)_once;

    const size_t proj_off = (size_t)QKVN * DIMC;

    prep_w_kernel<<<(QKVN * DIMC + 255) / 256, 256>>>(qkv_w, w16, DIMC, QKVN);
    prep_w_kernel<<<(DIMC * DIMC + 255) / 256, 256>>>(
        proj_w, w16 + proj_off, DIMC, DIMC);
    prep_comb_kernel<<<(NWIN * HEADS * NTOK * 64 + 255) / 256, 256>>>(
        mask, rel_table, rel_index, combbuf);
    {
        const size_t n4 = (size_t)MROWS * DIMC / 4;
        prep_x_kernel<<<(unsigned)((n4 + 255) / 256), 256>>>(x, x16, n4);
    }

    {   // QKV GEMM (fp16 1-MMA) -> single fp16 qkv
        dim3 grid(QKVN / 128, MROWS / 128);  // (9, 1568)
        mma_gemm<true, true><<<grid, 256, GEMM_SMEM_BYTES>>>(
            x16, w16, qkv_b, nullptr, q16, MROWS, QKVN, DIMC);
    }

    attn_mma_kernel<<<BWIN * 3, 128, ATTN_SMEM_BYTES>>>(q16, combbuf, a16);

    {   // proj GEMM (fp16 1-MMA) -> fp32 out
        dim3 grid(DIMC / 128, MROWS / 128);  // (3, 1568)
        mma_gemm<false, false><<<grid, 256, GEMM_SMEM_BYTES>>>(
            a16, w16 + proj_off, proj_b, out, nullptr, MROWS, DIMC, DIMC);
    }
}